// round 1
// baseline (speedup 1.0000x reference)
#include <cuda_runtime.h>
#include <math.h>

#define NNODE 30000
#define NEDGE 300000
#define ETOT  330000      // NEDGE + NNODE self loops
#define NB    300
#define EMB   64
#define D1    256         // HEADS*EMB
#define H12   4
#define H3    6
#define OUT3  121
#define D3    726         // H3*OUT3
#define NCLS  10

// ---------------- scratch (static device globals; no runtime allocation) ----
__device__ float    g_feat[NNODE * D1];   // layer input features
__device__ float    g_proj[NNODE * D3];   // projected h = x@W
__device__ float    g_aggr[NNODE * D3];   // aggregated output
__device__ float    g_es  [NNODE * H3];
__device__ float    g_ed  [NNODE * H3];
__device__ unsigned g_menc[NNODE * H3];   // order-encoded float max
__device__ float    g_sum [NNODE * H3];   // softmax denominators
__device__ float    g_pool[NB * D3];
__device__ float    g_cnt [NB];

// order-preserving float <-> uint encoding (for atomicMax on floats incl. negatives)
__device__ __forceinline__ unsigned fenc(float f) {
    unsigned u = __float_as_uint(f);
    return (u & 0x80000000u) ? ~u : (u | 0x80000000u);
}
__device__ __forceinline__ float fdec(unsigned u) {
    return (u & 0x80000000u) ? __uint_as_float(u & 0x7fffffffu)
                             : __uint_as_float(~u);
}

// ---------------- utility kernels ------------------------------------------
__global__ void zero_f(float* p, int n) {
    for (int i = blockIdx.x * blockDim.x + threadIdx.x; i < n; i += gridDim.x * blockDim.x)
        p[i] = 0.f;
}
__global__ void zero_u(unsigned* p, int n) {
    for (int i = blockIdx.x * blockDim.x + threadIdx.x; i < n; i += gridDim.x * blockDim.x)
        p[i] = 0u;
}

// ---------------- node encoder ---------------------------------------------
__global__ void node_enc(const int* __restrict__ x, const int* __restrict__ nd,
                         const float* __restrict__ ne, const float* __restrict__ de,
                         float* __restrict__ out) {
    int i = blockIdx.x * blockDim.x + threadIdx.x;
    if (i >= NNODE * EMB) return;
    int n = i >> 6, d = i & 63;
    out[i] = ne[x[n] * EMB + d] + de[nd[n] * EMB + d];
}

// ---------------- tiled SGEMM: C[M,N] = A[M,K] @ B[K,N] ---------------------
// BM=BN=64, BK=16, 256 threads, 4x4 per thread
__global__ void gemm64(const float* __restrict__ A, const float* __restrict__ B,
                       float* __restrict__ C, int M, int K, int N) {
    __shared__ float As[16][64];
    __shared__ float Bs[16][64];
    int tid = threadIdx.x;
    int tx = tid & 15, ty = tid >> 4;
    int bm = blockIdx.y * 64, bn = blockIdx.x * 64;
    float acc[4][4] = {};
    for (int k0 = 0; k0 < K; k0 += 16) {
#pragma unroll
        for (int i = 0; i < 4; i++) {
            int idx = tid * 4 + i;
            int r = idx >> 4, c = idx & 15;
            int gr = bm + r, gc = k0 + c;
            As[c][r] = (gr < M && gc < K) ? A[(long)gr * K + gc] : 0.f;
        }
#pragma unroll
        for (int i = 0; i < 4; i++) {
            int idx = tid * 4 + i;
            int r = idx >> 6, c = idx & 63;
            int gr = k0 + r, gc = bn + c;
            Bs[r][c] = (gr < K && gc < N) ? B[(long)gr * N + gc] : 0.f;
        }
        __syncthreads();
#pragma unroll
        for (int kk = 0; kk < 16; kk++) {
            float a[4], b[4];
#pragma unroll
            for (int i = 0; i < 4; i++) a[i] = As[kk][ty * 4 + i];
#pragma unroll
            for (int j = 0; j < 4; j++) b[j] = Bs[kk][tx * 4 + j];
#pragma unroll
            for (int i = 0; i < 4; i++)
#pragma unroll
                for (int j = 0; j < 4; j++) acc[i][j] += a[i] * b[j];
        }
        __syncthreads();
    }
#pragma unroll
    for (int i = 0; i < 4; i++)
#pragma unroll
        for (int j = 0; j < 4; j++) {
            int r = bm + ty * 4 + i, c = bn + tx * 4 + j;
            if (r < M && c < N) C[(long)r * N + c] = acc[i][j];
        }
}

// ---------------- per-node attention coefficients (warp per node,head) ------
template <int H, int D>
__global__ void attn_coef(const float* __restrict__ proj, const float* __restrict__ as,
                          const float* __restrict__ ad, float* __restrict__ es,
                          float* __restrict__ ed) {
    int gw = (blockIdx.x * blockDim.x + threadIdx.x) >> 5;
    int lane = threadIdx.x & 31;
    if (gw >= NNODE * H) return;
    int n = gw / H, h = gw - n * H;
    const float* row = proj + (long)n * (H * D) + h * D;
    const float* a1 = as + h * D;
    const float* a2 = ad + h * D;
    float s1 = 0.f, s2 = 0.f;
    for (int d = lane; d < D; d += 32) {
        float p = row[d];
        s1 += p * a1[d];
        s2 += p * a2[d];
    }
#pragma unroll
    for (int o = 16; o; o >>= 1) {
        s1 += __shfl_xor_sync(0xffffffffu, s1, o);
        s2 += __shfl_xor_sync(0xffffffffu, s2, o);
    }
    if (lane == 0) { es[n * H + h] = s1; ed[n * H + h] = s2; }
}

// ---------------- edge kernels ---------------------------------------------
template <int H>
__global__ void edge_max(const int* __restrict__ ei, const float* __restrict__ es,
                         const float* __restrict__ ed, unsigned* __restrict__ menc) {
    int e = blockIdx.x * blockDim.x + threadIdx.x;
    if (e >= ETOT) return;
    int s_, d_;
    if (e < NEDGE) { s_ = ei[e]; d_ = ei[NEDGE + e]; }
    else           { s_ = d_ = e - NEDGE; }
#pragma unroll
    for (int h = 0; h < H; h++) {
        float v = es[s_ * H + h] + ed[d_ * H + h];
        v = v > 0.f ? v : 0.2f * v;
        atomicMax(&menc[d_ * H + h], fenc(v));
    }
}

template <int H>
__global__ void edge_sum(const int* __restrict__ ei, const float* __restrict__ es,
                         const float* __restrict__ ed, const unsigned* __restrict__ menc,
                         float* __restrict__ ssum) {
    int e = blockIdx.x * blockDim.x + threadIdx.x;
    if (e >= ETOT) return;
    int s_, d_;
    if (e < NEDGE) { s_ = ei[e]; d_ = ei[NEDGE + e]; }
    else           { s_ = d_ = e - NEDGE; }
#pragma unroll
    for (int h = 0; h < H; h++) {
        float v = es[s_ * H + h] + ed[d_ * H + h];
        v = v > 0.f ? v : 0.2f * v;
        atomicAdd(&ssum[d_ * H + h], __expf(v - fdec(menc[d_ * H + h])));
    }
}

// warp per edge: alpha per head in lanes 0..H-1, broadcast, coalesced atomics
template <int H, int D>
__global__ void edge_agg(const int* __restrict__ ei, const float* __restrict__ proj,
                         const float* __restrict__ es, const float* __restrict__ ed,
                         const unsigned* __restrict__ menc, const float* __restrict__ ssum,
                         float* __restrict__ aggr) {
    const int Dout = H * D;
    int gw = (blockIdx.x * blockDim.x + threadIdx.x) >> 5;
    int lane = threadIdx.x & 31;
    if (gw >= ETOT) return;
    int s_, d_;
    if (gw < NEDGE) { s_ = ei[gw]; d_ = ei[NEDGE + gw]; }
    else            { s_ = d_ = gw - NEDGE; }
    float alpha = 0.f;
    if (lane < H) {
        float v = es[s_ * H + lane] + ed[d_ * H + lane];
        v = v > 0.f ? v : 0.2f * v;
        float ex = __expf(v - fdec(menc[d_ * H + lane]));
        alpha = ex / (ssum[d_ * H + lane] + 1e-16f);
    }
    const float* prow = proj + (long)s_ * Dout;
    float* arow = aggr + (long)d_ * Dout;
    for (int j0 = 0; j0 < Dout; j0 += 32) {
        int j = j0 + lane;
        int head = (j < Dout ? j : Dout - 1) / D;
        float a = __shfl_sync(0xffffffffu, alpha, head);
        if (j < Dout) atomicAdd(&arow[j], prow[j] * a);
    }
}

// ---------------- bias + optional ELU --------------------------------------
__global__ void epilogue(const float* __restrict__ aggr, const float* __restrict__ bias,
                         float* __restrict__ out, int Dout, int total, int elu) {
    int i = blockIdx.x * blockDim.x + threadIdx.x;
    if (i >= total) return;
    int j = i % Dout;
    float v = aggr[i] + bias[j];
    if (elu) v = v > 0.f ? v : expm1f(v);
    out[i] = v;
}

// ---------------- pooling + head -------------------------------------------
__global__ void pool_feat(const float* __restrict__ aggr, const int* __restrict__ batch,
                          float* __restrict__ pool) {
    int i = blockIdx.x * blockDim.x + threadIdx.x;
    if (i >= NNODE * D3) return;
    int n = i / D3, j = i - n * D3;
    atomicAdd(&pool[batch[n] * D3 + j], aggr[i]);
}
__global__ void pool_cnt(const int* __restrict__ batch, float* __restrict__ cnt) {
    int n = blockIdx.x * blockDim.x + threadIdx.x;
    if (n < NNODE) atomicAdd(&cnt[batch[n]], 1.f);
}
__global__ void head_kernel(const float* __restrict__ pool, const float* __restrict__ cnt,
                            const float* __restrict__ wp, const float* __restrict__ bp,
                            float* __restrict__ out) {
    __shared__ float gm[OUT3];
    int b = blockIdx.x;
    float inv = 1.f / fmaxf(cnt[b], 1.f);
    for (int o = threadIdx.x; o < OUT3; o += blockDim.x) {
        float s = 0.f;
#pragma unroll
        for (int h = 0; h < H3; h++) s += pool[b * D3 + h * OUT3 + o];
        gm[o] = s * inv * (1.f / H3);
    }
    __syncthreads();
    if (threadIdx.x < NCLS) {
        float acc = bp[threadIdx.x];
        for (int o = 0; o < OUT3; o++) acc += gm[o] * wp[o * NCLS + threadIdx.x];
        out[b * NCLS + threadIdx.x] = acc;
    }
}

// ---------------- host orchestration ---------------------------------------
extern "C" void kernel_launch(void* const* d_in, const int* in_sizes, int n_in,
                              void* d_out, int out_size) {
    const int*   x    = (const int*)d_in[0];
    const int*   nd   = (const int*)d_in[1];
    const int*   ei   = (const int*)d_in[2];
    const int*   bat  = (const int*)d_in[3];
    const float* nemb = (const float*)d_in[4];
    const float* demb = (const float*)d_in[5];
    const float* w1   = (const float*)d_in[6];
    const float* as1  = (const float*)d_in[7];
    const float* ad1  = (const float*)d_in[8];
    const float* b1   = (const float*)d_in[9];
    const float* w2   = (const float*)d_in[10];
    const float* as2  = (const float*)d_in[11];
    const float* ad2  = (const float*)d_in[12];
    const float* b2   = (const float*)d_in[13];
    const float* w3   = (const float*)d_in[14];
    const float* as3  = (const float*)d_in[15];
    const float* ad3  = (const float*)d_in[16];
    const float* b3   = (const float*)d_in[17];
    const float* wp   = (const float*)d_in[18];
    const float* bp   = (const float*)d_in[19];
    float* out = (float*)d_out;

    float *feat, *proj, *aggr, *es, *ed, *ssum, *pool, *cnt;
    unsigned* menc;
    cudaGetSymbolAddress((void**)&feat, g_feat);
    cudaGetSymbolAddress((void**)&proj, g_proj);
    cudaGetSymbolAddress((void**)&aggr, g_aggr);
    cudaGetSymbolAddress((void**)&es,   g_es);
    cudaGetSymbolAddress((void**)&ed,   g_ed);
    cudaGetSymbolAddress((void**)&menc, g_menc);
    cudaGetSymbolAddress((void**)&ssum, g_sum);
    cudaGetSymbolAddress((void**)&pool, g_pool);
    cudaGetSymbolAddress((void**)&cnt,  g_cnt);

    const int TB = 256;
    const int eb = (ETOT + TB - 1) / TB;

    // node encoder -> feat[:, :64]
    node_enc<<<(NNODE * EMB + TB - 1) / TB, TB>>>(x, nd, nemb, demb, feat);

    // ---- layer 1: in=feat(K=64), H=4, D=64, Dout=256 ----
    {
        dim3 g((D1 + 63) / 64, (NNODE + 63) / 64);
        gemm64<<<g, 256>>>(feat, w1, proj, NNODE, EMB, D1);
        attn_coef<H12, EMB><<<(NNODE * H12 * 32 + TB - 1) / TB, TB>>>(proj, as1, ad1, es, ed);
        zero_u<<<128, TB>>>(menc, NNODE * H12);
        zero_f<<<128, TB>>>(ssum, NNODE * H12);
        zero_f<<<2048, TB>>>(aggr, NNODE * D1);
        edge_max<H12><<<eb, TB>>>(ei, es, ed, menc);
        edge_sum<H12><<<eb, TB>>>(ei, es, ed, menc, ssum);
        edge_agg<H12, EMB><<<(ETOT * 32 + TB - 1) / TB, TB>>>(ei, proj, es, ed, menc, ssum, aggr);
        epilogue<<<(NNODE * D1 + TB - 1) / TB, TB>>>(aggr, b1, feat, D1, NNODE * D1, 1);
    }

    // ---- layer 2: in=feat(K=256), H=4, D=64, Dout=256 ----
    {
        dim3 g((D1 + 63) / 64, (NNODE + 63) / 64);
        gemm64<<<g, 256>>>(feat, w2, proj, NNODE, D1, D1);
        attn_coef<H12, EMB><<<(NNODE * H12 * 32 + TB - 1) / TB, TB>>>(proj, as2, ad2, es, ed);
        zero_u<<<128, TB>>>(menc, NNODE * H12);
        zero_f<<<128, TB>>>(ssum, NNODE * H12);
        zero_f<<<2048, TB>>>(aggr, NNODE * D1);
        edge_max<H12><<<eb, TB>>>(ei, es, ed, menc);
        edge_sum<H12><<<eb, TB>>>(ei, es, ed, menc, ssum);
        edge_agg<H12, EMB><<<(ETOT * 32 + TB - 1) / TB, TB>>>(ei, proj, es, ed, menc, ssum, aggr);
        epilogue<<<(NNODE * D1 + TB - 1) / TB, TB>>>(aggr, b2, feat, D1, NNODE * D1, 1);
    }

    // ---- layer 3: in=feat(K=256), H=6, D=121, Dout=726 ----
    {
        dim3 g((D3 + 63) / 64, (NNODE + 63) / 64);
        gemm64<<<g, 256>>>(feat, w3, proj, NNODE, D1, D3);
        attn_coef<H3, OUT3><<<(NNODE * H3 * 32 + TB - 1) / TB, TB>>>(proj, as3, ad3, es, ed);
        zero_u<<<128, TB>>>(menc, NNODE * H3);
        zero_f<<<128, TB>>>(ssum, NNODE * H3);
        zero_f<<<4096, TB>>>(aggr, NNODE * D3);
        edge_max<H3><<<eb, TB>>>(ei, es, ed, menc);
        edge_sum<H3><<<eb, TB>>>(ei, es, ed, menc, ssum);
        edge_agg<H3, OUT3><<<(ETOT * 32 + TB - 1) / TB, TB>>>(ei, proj, es, ed, menc, ssum, aggr);
        epilogue<<<(NNODE * D3 + TB - 1) / TB, TB>>>(aggr, b3, aggr, D3, NNODE * D3, 0);
    }

    // ---- pooling + classifier head ----
    zero_f<<<64, TB>>>(pool, NB * D3);
    zero_f<<<1, TB>>>(cnt, NB);
    pool_feat<<<(NNODE * D3 + TB - 1) / TB, TB>>>(aggr, bat, pool);
    pool_cnt<<<(NNODE + TB - 1) / TB, TB>>>(bat, cnt);
    head_kernel<<<NB, 128>>>(pool, cnt, wp, bp, out);
}

// round 3
// speedup vs baseline: 1.1927x; 1.1927x over previous
#include <cuda_runtime.h>
#include <math.h>

#define NNODE 30000
#define NEDGE 300000
#define ETOT  330000      // NEDGE + NNODE self loops
#define NB    300
#define EMB   64
#define D1    256         // HEADS*EMB
#define H12   4
#define H3    6
#define OUT3  121
#define D3    726         // H3*OUT3
#define D3P   768         // padded: head stride 128
#define NCLS  10

// ---------------- scratch (static device globals) ---------------------------
__device__ float    g_feat[NNODE * D1];
__device__ float    g_proj[NNODE * D3P];
__device__ float    g_aggr[NNODE * D3P];
__device__ float    g_es  [NNODE * H3];
__device__ float    g_ed  [NNODE * H3];
__device__ unsigned g_menc[NNODE * H3];
__device__ float    g_sum [NNODE * H3];
__device__ float    g_eval[ETOT * H3];     // edge logits -> exp values
__device__ float    g_w3p [D1 * D3P];      // padded w3
__device__ float    g_b3p [D3P];
__device__ float    g_pool[NB * D3P];
__device__ float    g_cnt [NB];

// order-preserving float <-> uint encoding
__device__ __forceinline__ unsigned fenc(float f) {
    unsigned u = __float_as_uint(f);
    return (u & 0x80000000u) ? ~u : (u | 0x80000000u);
}
__device__ __forceinline__ float fdec(unsigned u) {
    return (u & 0x80000000u) ? __uint_as_float(u & 0x7fffffffu)
                             : __uint_as_float(~u);
}

__device__ __forceinline__ void red_v4(float4* addr, float4 v) {
    asm volatile("red.global.add.v4.f32 [%0], {%1,%2,%3,%4};" ::
                 "l"(addr), "f"(v.x), "f"(v.y), "f"(v.z), "f"(v.w) : "memory");
}

// ---------------- node encoder ---------------------------------------------
__global__ void node_enc(const int* __restrict__ x, const int* __restrict__ nd,
                         const float* __restrict__ ne, const float* __restrict__ de,
                         float* __restrict__ out) {
    int i = blockIdx.x * blockDim.x + threadIdx.x;
    if (i >= NNODE * EMB) return;
    int n = i >> 6, d = i & 63;
    out[i] = ne[x[n] * EMB + d] + de[nd[n] * EMB + d];
}

// ---------------- pad w3/b3 to head-stride 128 ------------------------------
__global__ void pad_w3(const float* __restrict__ w3, const float* __restrict__ b3,
                       float* __restrict__ w3p, float* __restrict__ b3p) {
    int i = blockIdx.x * blockDim.x + threadIdx.x;
    if (i < D1 * D3P) {
        int rowk = i / D3P, col = i - rowk * D3P;
        int h = col >> 7, o = col & 127;
        w3p[i] = (o < OUT3) ? w3[rowk * D3 + h * OUT3 + o] : 0.f;
    }
    if (i < D3P) {
        int h = i >> 7, o = i & 127;
        b3p[i] = (o < OUT3) ? b3[h * OUT3 + o] : 0.f;
    }
}

// ---------------- SGEMM 128x128, BK=16, 8x8/thread, float4 ------------------
// requires: K % 16 == 0, N % 128 == 0 per launch grid (we only use N=256,768)
__global__ void gemm128(const float* __restrict__ A, const float* __restrict__ B,
                        float* __restrict__ C, int M, int K, int N) {
    __shared__ float As[16][128];
    __shared__ float Bs[16][128];
    int t = threadIdx.x;
    int tx = t & 15, ty = t >> 4;
    int bm = blockIdx.y * 128, bn = blockIdx.x * 128;
    float acc[8][8] = {};
    for (int k0 = 0; k0 < K; k0 += 16) {
#pragma unroll
        for (int i = 0; i < 2; i++) {
            int f = t + i * 256;
            int row = f >> 2, kc = (f & 3) * 4;
            float4 v = make_float4(0.f, 0.f, 0.f, 0.f);
            int gr = bm + row;
            if (gr < M) v = *(const float4*)&A[(long)gr * K + k0 + kc];
            As[kc + 0][row] = v.x; As[kc + 1][row] = v.y;
            As[kc + 2][row] = v.z; As[kc + 3][row] = v.w;
        }
#pragma unroll
        for (int i = 0; i < 2; i++) {
            int f = t + i * 256;
            int row = f >> 5, c4 = (f & 31) * 4;
            *(float4*)&Bs[row][c4] = *(const float4*)&B[(long)(k0 + row) * N + bn + c4];
        }
        __syncthreads();
#pragma unroll
        for (int kk = 0; kk < 16; kk++) {
            float a[8], b[8];
            *(float4*)&a[0] = *(float4*)&As[kk][ty * 8];
            *(float4*)&a[4] = *(float4*)&As[kk][ty * 8 + 4];
            *(float4*)&b[0] = *(float4*)&Bs[kk][tx * 8];
            *(float4*)&b[4] = *(float4*)&Bs[kk][tx * 8 + 4];
#pragma unroll
            for (int i = 0; i < 8; i++)
#pragma unroll
                for (int j = 0; j < 8; j++) acc[i][j] += a[i] * b[j];
        }
        __syncthreads();
    }
#pragma unroll
    for (int i = 0; i < 8; i++) {
        int r = bm + ty * 8 + i;
        if (r < M) {
            *(float4*)&C[(long)r * N + bn + tx * 8]     = *(float4*)&acc[i][0];
            *(float4*)&C[(long)r * N + bn + tx * 8 + 4] = *(float4*)&acc[i][4];
        }
    }
}

// ---------------- per-node attention coefficients ---------------------------
template <int H, int D, int ROWSTR, int HSTR>
__global__ void attn_coef(const float* __restrict__ proj, const float* __restrict__ as,
                          const float* __restrict__ ad, float* __restrict__ es,
                          float* __restrict__ ed) {
    int gw = (blockIdx.x * blockDim.x + threadIdx.x) >> 5;
    int lane = threadIdx.x & 31;
    if (gw >= NNODE * H) return;
    int n = gw / H, h = gw - n * H;
    const float* row = proj + (long)n * ROWSTR + h * HSTR;
    const float* a1 = as + h * D;
    const float* a2 = ad + h * D;
    float s1 = 0.f, s2 = 0.f;
    for (int d = lane; d < D; d += 32) {
        float p = row[d];
        s1 += p * a1[d];
        s2 += p * a2[d];
    }
#pragma unroll
    for (int o = 16; o; o >>= 1) {
        s1 += __shfl_xor_sync(0xffffffffu, s1, o);
        s2 += __shfl_xor_sync(0xffffffffu, s2, o);
    }
    if (lane == 0) { es[n * H + h] = s1; ed[n * H + h] = s2; }
}

// ---------------- edge pass 1: logits + segment max -------------------------
template <int H>
__global__ void edge_logits(const int* __restrict__ ei, const float* __restrict__ es,
                            const float* __restrict__ ed, float* __restrict__ eval,
                            unsigned* __restrict__ menc) {
    int e = blockIdx.x * blockDim.x + threadIdx.x;
    if (e >= ETOT) return;
    int s_, d_;
    if (e < NEDGE) { s_ = ei[e]; d_ = ei[NEDGE + e]; }
    else           { s_ = d_ = e - NEDGE; }
#pragma unroll
    for (int h = 0; h < H; h++) {
        float v = es[s_ * H + h] + ed[d_ * H + h];
        v = v > 0.f ? v : 0.2f * v;
        eval[e * H + h] = v;
        atomicMax(&menc[d_ * H + h], fenc(v));
    }
}

// ---------------- edge pass 2: exp + segment sum (overwrites eval) ----------
template <int H>
__global__ void edge_expsum(const int* __restrict__ ei, float* __restrict__ eval,
                            const unsigned* __restrict__ menc, float* __restrict__ ssum) {
    int e = blockIdx.x * blockDim.x + threadIdx.x;
    if (e >= ETOT) return;
    int d_ = (e < NEDGE) ? ei[NEDGE + e] : e - NEDGE;
#pragma unroll
    for (int h = 0; h < H; h++) {
        float ex = __expf(eval[e * H + h] - fdec(menc[d_ * H + h]));
        eval[e * H + h] = ex;
        atomicAdd(&ssum[d_ * H + h], ex);
    }
}

// ---------------- edge pass 3: aggregate (warp/edge, float4 vector atomics) -
template <int H, int D4H>   // D4H = float4s per head; Dout/4 = H*D4H
__global__ void edge_agg_v4(const int* __restrict__ ei, const float4* __restrict__ proj,
                            const float* __restrict__ eval, const float* __restrict__ ssum,
                            float4* __restrict__ aggr) {
    const int DoutV = H * D4H;
    int gw = (blockIdx.x * blockDim.x + threadIdx.x) >> 5;
    int lane = threadIdx.x & 31;
    if (gw >= ETOT) return;
    int s_, d_;
    if (gw < NEDGE) { s_ = ei[gw]; d_ = ei[NEDGE + gw]; }
    else            { s_ = d_ = gw - NEDGE; }
    float alpha = 0.f;
    if (lane < H)
        alpha = eval[gw * H + lane] / (ssum[d_ * H + lane] + 1e-16f);
    const float4* prow = proj + (long)s_ * DoutV;
    float4* arow = aggr + (long)d_ * DoutV;
#pragma unroll
    for (int j4 = lane; j4 < DoutV; j4 += 32) {
        float a = __shfl_sync(0xffffffffu, alpha, j4 / D4H);
        float4 p = __ldg(&prow[j4]);
        red_v4(&arow[j4], make_float4(p.x * a, p.y * a, p.z * a, p.w * a));
    }
}

// ---------------- bias + optional ELU --------------------------------------
__global__ void epilogue(const float* __restrict__ aggr, const float* __restrict__ bias,
                         float* __restrict__ out, int Dout, int total, int elu) {
    int i = blockIdx.x * blockDim.x + threadIdx.x;
    if (i >= total) return;
    int j = i % Dout;
    float v = aggr[i] + bias[j];
    if (elu) v = v > 0.f ? v : expm1f(v);
    out[i] = v;
}

// ---------------- pooling + head -------------------------------------------
__global__ void pool_feat_v4(const float4* __restrict__ aggr, const int* __restrict__ batch,
                             float4* __restrict__ pool) {
    const int RV = D3P / 4;
    int i = blockIdx.x * blockDim.x + threadIdx.x;
    if (i >= NNODE * RV) return;
    int n = i / RV, j = i - n * RV;
    red_v4(&pool[batch[n] * RV + j], aggr[i]);
}
__global__ void pool_cnt(const int* __restrict__ batch, float* __restrict__ cnt) {
    int n = blockIdx.x * blockDim.x + threadIdx.x;
    if (n < NNODE) atomicAdd(&cnt[batch[n]], 1.f);
}
__global__ void head_kernel(const float* __restrict__ pool, const float* __restrict__ cnt,
                            const float* __restrict__ wp, const float* __restrict__ bp,
                            float* __restrict__ out) {
    __shared__ float gm[OUT3];
    int b = blockIdx.x;
    float inv = 1.f / fmaxf(cnt[b], 1.f);
    for (int o = threadIdx.x; o < OUT3; o += blockDim.x) {
        float s = 0.f;
#pragma unroll
        for (int h = 0; h < H3; h++) s += pool[b * D3P + h * 128 + o];
        gm[o] = s * inv * (1.f / H3);
    }
    __syncthreads();
    if (threadIdx.x < NCLS) {
        float acc = bp[threadIdx.x];
        for (int o = 0; o < OUT3; o++) acc += gm[o] * wp[o * NCLS + threadIdx.x];
        out[b * NCLS + threadIdx.x] = acc;
    }
}

// ---------------- host orchestration ---------------------------------------
extern "C" void kernel_launch(void* const* d_in, const int* in_sizes, int n_in,
                              void* d_out, int out_size) {
    const int*   x    = (const int*)d_in[0];
    const int*   nd   = (const int*)d_in[1];
    const int*   ei   = (const int*)d_in[2];
    const int*   bat  = (const int*)d_in[3];
    const float* nemb = (const float*)d_in[4];
    const float* demb = (const float*)d_in[5];
    const float* w1   = (const float*)d_in[6];
    const float* as1  = (const float*)d_in[7];
    const float* ad1  = (const float*)d_in[8];
    const float* b1   = (const float*)d_in[9];
    const float* w2   = (const float*)d_in[10];
    const float* as2  = (const float*)d_in[11];
    const float* ad2  = (const float*)d_in[12];
    const float* b2   = (const float*)d_in[13];
    const float* w3   = (const float*)d_in[14];
    const float* as3  = (const float*)d_in[15];
    const float* ad3  = (const float*)d_in[16];
    const float* b3   = (const float*)d_in[17];
    const float* wp   = (const float*)d_in[18];
    const float* bp   = (const float*)d_in[19];
    float* out = (float*)d_out;

    float *feat, *proj, *aggr, *es, *ed, *ssum, *eval, *w3p, *b3p, *pool, *cnt;
    unsigned* menc;
    cudaGetSymbolAddress((void**)&feat, g_feat);
    cudaGetSymbolAddress((void**)&proj, g_proj);
    cudaGetSymbolAddress((void**)&aggr, g_aggr);
    cudaGetSymbolAddress((void**)&es,   g_es);
    cudaGetSymbolAddress((void**)&ed,   g_ed);
    cudaGetSymbolAddress((void**)&menc, g_menc);
    cudaGetSymbolAddress((void**)&ssum, g_sum);
    cudaGetSymbolAddress((void**)&eval, g_eval);
    cudaGetSymbolAddress((void**)&w3p,  g_w3p);
    cudaGetSymbolAddress((void**)&b3p,  g_b3p);
    cudaGetSymbolAddress((void**)&pool, g_pool);
    cudaGetSymbolAddress((void**)&cnt,  g_cnt);

    const int TB = 256;
    const int eb = (ETOT + TB - 1) / TB;
    const int wb = (ETOT * 32) / TB;   // ETOT*32 divisible by 256

    node_enc<<<(NNODE * EMB + TB - 1) / TB, TB>>>(x, nd, nemb, demb, feat);
    pad_w3<<<(D1 * D3P + TB - 1) / TB, TB>>>(w3, b3, w3p, b3p);

    // ---- layer 1: K=64 -> Dout=256, H=4, D=64 ----
    {
        dim3 g(D1 / 128, (NNODE + 127) / 128);
        gemm128<<<g, 256>>>(feat, w1, proj, NNODE, EMB, D1);
        attn_coef<H12, EMB, D1, EMB><<<(NNODE * H12 * 32 + TB - 1) / TB, TB>>>(proj, as1, ad1, es, ed);
        cudaMemsetAsync(menc, 0, NNODE * H12 * 4);
        cudaMemsetAsync(ssum, 0, NNODE * H12 * 4);
        cudaMemsetAsync(aggr, 0, (size_t)NNODE * D1 * 4);
        edge_logits<H12><<<eb, TB>>>(ei, es, ed, eval, menc);
        edge_expsum<H12><<<eb, TB>>>(ei, eval, menc, ssum);
        edge_agg_v4<H12, 16><<<wb, TB>>>(ei, (const float4*)proj, eval, ssum, (float4*)aggr);
        epilogue<<<(NNODE * D1 + TB - 1) / TB, TB>>>(aggr, b1, feat, D1, NNODE * D1, 1);
    }

    // ---- layer 2: K=256 -> Dout=256, H=4, D=64 ----
    {
        dim3 g(D1 / 128, (NNODE + 127) / 128);
        gemm128<<<g, 256>>>(feat, w2, proj, NNODE, D1, D1);
        attn_coef<H12, EMB, D1, EMB><<<(NNODE * H12 * 32 + TB - 1) / TB, TB>>>(proj, as2, ad2, es, ed);
        cudaMemsetAsync(menc, 0, NNODE * H12 * 4);
        cudaMemsetAsync(ssum, 0, NNODE * H12 * 4);
        cudaMemsetAsync(aggr, 0, (size_t)NNODE * D1 * 4);
        edge_logits<H12><<<eb, TB>>>(ei, es, ed, eval, menc);
        edge_expsum<H12><<<eb, TB>>>(ei, eval, menc, ssum);
        edge_agg_v4<H12, 16><<<wb, TB>>>(ei, (const float4*)proj, eval, ssum, (float4*)aggr);
        epilogue<<<(NNODE * D1 + TB - 1) / TB, TB>>>(aggr, b2, feat, D1, NNODE * D1, 1);
    }

    // ---- layer 3 (padded): K=256 -> Dout=768 (head stride 128), H=6, D=121 --
    {
        dim3 g(D3P / 128, (NNODE + 127) / 128);
        gemm128<<<g, 256>>>(feat, w3p, proj, NNODE, D1, D3P);
        attn_coef<H3, OUT3, D3P, 128><<<(NNODE * H3 * 32 + TB - 1) / TB, TB>>>(proj, as3, ad3, es, ed);
        cudaMemsetAsync(menc, 0, NNODE * H3 * 4);
        cudaMemsetAsync(ssum, 0, NNODE * H3 * 4);
        cudaMemsetAsync(aggr, 0, (size_t)NNODE * D3P * 4);
        edge_logits<H3><<<eb, TB>>>(ei, es, ed, eval, menc);
        edge_expsum<H3><<<eb, TB>>>(ei, eval, menc, ssum);
        edge_agg_v4<H3, 32><<<wb, TB>>>(ei, (const float4*)proj, eval, ssum, (float4*)aggr);
        epilogue<<<((size_t)NNODE * D3P + TB - 1) / TB, TB>>>(aggr, b3p, aggr, D3P, NNODE * D3P, 0);
    }

    // ---- pooling + classifier head ----
    cudaMemsetAsync(pool, 0, NB * D3P * 4);
    cudaMemsetAsync(cnt, 0, NB * 4);
    pool_feat_v4<<<(NNODE * (D3P / 4) + TB - 1) / TB, TB>>>((const float4*)aggr, bat, (float4*)pool);
    pool_cnt<<<(NNODE + TB - 1) / TB, TB>>>(bat, cnt);
    head_kernel<<<NB, 128>>>(pool, cnt, wp, bp, out);
}

// round 4
// speedup vs baseline: 2.3962x; 2.0090x over previous
#include <cuda_runtime.h>
#include <math.h>

#define NNODE 30000
#define NEDGE 300000
#define ETOT  330000      // NEDGE + NNODE self loops
#define NB    300
#define EMB   64
#define D1    256         // HEADS*EMB
#define H12   4
#define H3    6
#define OUT3  121
#define D3    726
#define D3P   768         // padded: head stride 128
#define NCLS  10

// ---------------- scratch (static device globals) ---------------------------
__device__ float g_feat[NNODE * D1];
__device__ float g_proj[NNODE * D3P];
__device__ float g_aggr[NNODE * D3P];
__device__ float g_es  [NNODE * H3];
__device__ float g_ed  [NNODE * H3];
__device__ float g_w3p [D1 * D3P];
__device__ float g_b3p [D3P];
__device__ float g_pool[NB * D3P];
__device__ float g_cnt [NB];
__device__ int   g_deg [NNODE];
__device__ int   g_off [NNODE + 1];
__device__ int   g_cur [NNODE];
__device__ int   g_csrc[ETOT];

__device__ __forceinline__ unsigned f2tf(float x) {
    unsigned r;
    asm("cvt.rna.tf32.f32 %0, %1;" : "=r"(r) : "f"(x));
    return r;
}
__device__ __forceinline__ void red_v4(float4* addr, float4 v) {
    asm volatile("red.global.add.v4.f32 [%0], {%1,%2,%3,%4};" ::
                 "l"(addr), "f"(v.x), "f"(v.y), "f"(v.z), "f"(v.w) : "memory");
}

// ---------------- node encoder ---------------------------------------------
__global__ void node_enc(const int* __restrict__ x, const int* __restrict__ nd,
                         const float* __restrict__ ne, const float* __restrict__ de,
                         float* __restrict__ out) {
    int i = blockIdx.x * blockDim.x + threadIdx.x;
    if (i >= NNODE * EMB) return;
    int n = i >> 6, d = i & 63;
    out[i] = ne[x[n] * EMB + d] + de[nd[n] * EMB + d];
}

// ---------------- pad w3/b3 to head-stride 128 ------------------------------
__global__ void pad_w3(const float* __restrict__ w3, const float* __restrict__ b3,
                       float* __restrict__ w3p, float* __restrict__ b3p) {
    int i = blockIdx.x * blockDim.x + threadIdx.x;
    if (i < D1 * D3P) {
        int rowk = i / D3P, col = i - rowk * D3P;
        int h = col >> 7, o = col & 127;
        w3p[i] = (o < OUT3) ? w3[rowk * D3 + h * OUT3 + o] : 0.f;
    }
    if (i < D3P) {
        int h = i >> 7, o = i & 127;
        b3p[i] = (o < OUT3) ? b3[h * OUT3 + o] : 0.f;
    }
}

// ---------------- CSR build --------------------------------------------------
__global__ void count_deg(const int* __restrict__ ei, int* __restrict__ deg) {
    int e = blockIdx.x * blockDim.x + threadIdx.x;
    if (e >= ETOT) return;
    int d = (e < NEDGE) ? ei[NEDGE + e] : e - NEDGE;
    atomicAdd(&deg[d], 1);
}

__global__ __launch_bounds__(1024) void scan_deg(const int* __restrict__ deg,
                                                 int* __restrict__ off) {
    const int CH = 30;   // 1024*30 = 30720 >= NNODE
    __shared__ int wsum[32];
    int t = threadIdx.x, lane = t & 31, w = t >> 5;
    int base = t * CH;
    int loc[CH];
    int s = 0;
#pragma unroll
    for (int i = 0; i < CH; i++) {
        int idx = base + i;
        loc[i] = s;
        s += (idx < NNODE) ? deg[idx] : 0;
    }
    int x = s;
#pragma unroll
    for (int o = 1; o < 32; o <<= 1) {
        int y = __shfl_up_sync(0xffffffffu, x, o);
        if (lane >= o) x += y;
    }
    if (lane == 31) wsum[w] = x;
    __syncthreads();
    if (w == 0) {
        int y = wsum[lane];
#pragma unroll
        for (int o = 1; o < 32; o <<= 1) {
            int z = __shfl_up_sync(0xffffffffu, y, o);
            if (lane >= o) y += z;
        }
        wsum[lane] = y;
    }
    __syncthreads();
    int excl = (w ? wsum[w - 1] : 0) + (x - s);
#pragma unroll
    for (int i = 0; i < CH; i++) {
        int idx = base + i;
        if (idx < NNODE) off[idx] = excl + loc[i];
    }
    if (t == 1023) off[NNODE] = wsum[31];
}

__global__ void scatter_edges(const int* __restrict__ ei, const int* __restrict__ off,
                              int* __restrict__ cur, int* __restrict__ csrc) {
    int e = blockIdx.x * blockDim.x + threadIdx.x;
    if (e >= ETOT) return;
    int s, d;
    if (e < NEDGE) { s = ei[e]; d = ei[NEDGE + e]; }
    else           { s = d = e - NEDGE; }
    int slot = off[d] + atomicAdd(&cur[d], 1);
    csrc[slot] = s;
}

// ---------------- tf32 tensor-core GEMM: C[M,N] = A[M,K] @ B[K,N] -----------
// BM=BN=128, BK=32, 256 threads, 8 warps (4x2), warp tile 32x64, mma m16n8k8
__global__ __launch_bounds__(256) void gemm_tf32(const float* __restrict__ A,
                                                 const float* __restrict__ B,
                                                 float* __restrict__ C,
                                                 int M, int K, int N) {
    __shared__ unsigned As[128 * 36];   // row-major [m][k], stride 36
    __shared__ unsigned Bs[32 * 136];   // row-major [k][n], stride 136
    int t = threadIdx.x;
    int warp = t >> 5, lane = t & 31;
    int tg = lane >> 2, t4 = lane & 3;
    int bm = blockIdx.y * 128, bn = blockIdx.x * 128;
    int wm = (warp & 3) * 32, wn = (warp >> 2) * 64;
    float c[2][8][4];
#pragma unroll
    for (int i = 0; i < 2; i++)
#pragma unroll
        for (int j = 0; j < 8; j++)
#pragma unroll
            for (int q = 0; q < 4; q++) c[i][j][q] = 0.f;

    for (int k0 = 0; k0 < K; k0 += 32) {
#pragma unroll
        for (int i = 0; i < 4; i++) {
            int v = t + 256 * i;
            int row = v >> 3, c4 = (v & 7) << 2;
            float4 f = make_float4(0.f, 0.f, 0.f, 0.f);
            int gr = bm + row;
            if (gr < M) f = *(const float4*)(A + (size_t)gr * K + k0 + c4);
            uint4 u = make_uint4(f2tf(f.x), f2tf(f.y), f2tf(f.z), f2tf(f.w));
            *(uint4*)(As + row * 36 + c4) = u;
        }
#pragma unroll
        for (int i = 0; i < 4; i++) {
            int v = t + 256 * i;
            int row = v >> 5, c4 = (v & 31) << 2;
            float4 f = *(const float4*)(B + (size_t)(k0 + row) * N + bn + c4);
            uint4 u = make_uint4(f2tf(f.x), f2tf(f.y), f2tf(f.z), f2tf(f.w));
            *(uint4*)(Bs + row * 136 + c4) = u;
        }
        __syncthreads();
#pragma unroll
        for (int ks = 0; ks < 4; ks++) {
            unsigned a[2][4], b[8][2];
#pragma unroll
            for (int i = 0; i < 2; i++) {
                int r = wm + 16 * i + tg;
                int kc = ks * 8 + t4;
                a[i][0] = As[r * 36 + kc];
                a[i][1] = As[(r + 8) * 36 + kc];
                a[i][2] = As[r * 36 + kc + 4];
                a[i][3] = As[(r + 8) * 36 + kc + 4];
            }
#pragma unroll
            for (int j = 0; j < 8; j++) {
                int cc = wn + 8 * j + tg;
                b[j][0] = Bs[(ks * 8 + t4) * 136 + cc];
                b[j][1] = Bs[(ks * 8 + t4 + 4) * 136 + cc];
            }
#pragma unroll
            for (int i = 0; i < 2; i++)
#pragma unroll
                for (int j = 0; j < 8; j++) {
                    asm volatile(
                        "mma.sync.aligned.m16n8k8.row.col.f32.tf32.tf32.f32 "
                        "{%0,%1,%2,%3}, {%4,%5,%6,%7}, {%8,%9}, {%0,%1,%2,%3};"
                        : "+f"(c[i][j][0]), "+f"(c[i][j][1]),
                          "+f"(c[i][j][2]), "+f"(c[i][j][3])
                        : "r"(a[i][0]), "r"(a[i][1]), "r"(a[i][2]), "r"(a[i][3]),
                          "r"(b[j][0]), "r"(b[j][1]));
                }
        }
        __syncthreads();
    }
#pragma unroll
    for (int i = 0; i < 2; i++)
#pragma unroll
        for (int j = 0; j < 8; j++) {
            int r = bm + wm + 16 * i + tg;
            int cc = bn + wn + 8 * j + t4 * 2;
            if (r < M)
                *(float2*)(C + (size_t)r * N + cc) = make_float2(c[i][j][0], c[i][j][1]);
            if (r + 8 < M)
                *(float2*)(C + (size_t)(r + 8) * N + cc) = make_float2(c[i][j][2], c[i][j][3]);
        }
}

// ---------------- per-node attention coefficients ---------------------------
template <int H, int D, int ROWSTR, int HSTR>
__global__ void attn_coef(const float* __restrict__ proj, const float* __restrict__ as,
                          const float* __restrict__ ad, float* __restrict__ es,
                          float* __restrict__ ed) {
    int gw = (blockIdx.x * blockDim.x + threadIdx.x) >> 5;
    int lane = threadIdx.x & 31;
    if (gw >= NNODE * H) return;
    int n = gw / H, h = gw - n * H;
    const float* row = proj + (long)n * ROWSTR + h * HSTR;
    const float* a1 = as + h * D;
    const float* a2 = ad + h * D;
    float s1 = 0.f, s2 = 0.f;
    for (int d = lane; d < D; d += 32) {
        float p = row[d];
        s1 += p * a1[d];
        s2 += p * a2[d];
    }
#pragma unroll
    for (int o = 16; o; o >>= 1) {
        s1 += __shfl_xor_sync(0xffffffffu, s1, o);
        s2 += __shfl_xor_sync(0xffffffffu, s2, o);
    }
    if (lane == 0) { es[n * H + h] = s1; ed[n * H + h] = s2; }
}

// ---------------- fused GAT aggregation: warp per dst node -------------------
// HSTR4 = head stride in float4s; FPL = float4s per lane (NV4/32)
template <int H, int HSTR4, int FPL>
__global__ void gat_agg(const int* __restrict__ off, const int* __restrict__ csrc,
                        const float* __restrict__ es, const float* __restrict__ ed,
                        const float4* __restrict__ proj, const float4* __restrict__ bias,
                        float4* __restrict__ outp, int elu) {
    const int NV4 = H * HSTR4;
    int gw = (blockIdx.x * blockDim.x + threadIdx.x) >> 5;
    int lane = threadIdx.x & 31;
    if (gw >= NNODE) return;
    int o0 = off[gw], o1 = off[gw + 1];
    float edv[H], m[H], sm[H];
#pragma unroll
    for (int h = 0; h < H; h++) {
        edv[h] = __ldg(&ed[gw * H + h]);
        m[h] = -1e30f;
        sm[h] = 0.f;
    }
    // pass 1: segment max
    for (int i = o0 + lane; i < o1; i += 32) {
        int s = __ldg(&csrc[i]);
#pragma unroll
        for (int h = 0; h < H; h++) {
            float v = __ldg(&es[s * H + h]) + edv[h];
            v = v > 0.f ? v : 0.2f * v;
            m[h] = fmaxf(m[h], v);
        }
    }
#pragma unroll
    for (int h = 0; h < H; h++)
#pragma unroll
        for (int o = 16; o; o >>= 1)
            m[h] = fmaxf(m[h], __shfl_xor_sync(0xffffffffu, m[h], o));
    // pass 2: exp-sum
    for (int i = o0 + lane; i < o1; i += 32) {
        int s = __ldg(&csrc[i]);
#pragma unroll
        for (int h = 0; h < H; h++) {
            float v = __ldg(&es[s * H + h]) + edv[h];
            v = v > 0.f ? v : 0.2f * v;
            sm[h] += __expf(v - m[h]);
        }
    }
#pragma unroll
    for (int h = 0; h < H; h++) {
#pragma unroll
        for (int o = 16; o; o >>= 1)
            sm[h] += __shfl_xor_sync(0xffffffffu, sm[h], o);
        sm[h] = 1.f / (sm[h] + 1e-16f);
    }
    // pass 3: aggregate into registers (no atomics)
    float4 acc[FPL];
#pragma unroll
    for (int tt = 0; tt < FPL; tt++) acc[tt] = make_float4(0.f, 0.f, 0.f, 0.f);
    for (int i = o0; i < o1; i++) {
        int s = __ldg(&csrc[i]);
        float alpha = 0.f;
        if (lane < H) {
            float v = __ldg(&es[s * H + lane]) + edv[lane];
            v = v > 0.f ? v : 0.2f * v;
            alpha = __expf(v - m[lane]) * sm[lane];
        }
        const float4* prow = proj + (size_t)s * NV4;
#pragma unroll
        for (int tt = 0; tt < FPL; tt++) {
            int j4 = lane + 32 * tt;
            float a = __shfl_sync(0xffffffffu, alpha, j4 / HSTR4);
            float4 p = __ldg(&prow[j4]);
            acc[tt].x += p.x * a;
            acc[tt].y += p.y * a;
            acc[tt].z += p.z * a;
            acc[tt].w += p.w * a;
        }
    }
    // fused bias + optional ELU + write
    float4* orow = outp + (size_t)gw * NV4;
#pragma unroll
    for (int tt = 0; tt < FPL; tt++) {
        int j4 = lane + 32 * tt;
        float4 b = __ldg(&bias[j4]);
        float4 v = acc[tt];
        v.x += b.x; v.y += b.y; v.z += b.z; v.w += b.w;
        if (elu) {
            v.x = v.x > 0.f ? v.x : expm1f(v.x);
            v.y = v.y > 0.f ? v.y : expm1f(v.y);
            v.z = v.z > 0.f ? v.z : expm1f(v.z);
            v.w = v.w > 0.f ? v.w : expm1f(v.w);
        }
        orow[j4] = v;
    }
}

// ---------------- pooling + head --------------------------------------------
__global__ void pool_feat_v4(const float4* __restrict__ aggr, const int* __restrict__ batch,
                             float4* __restrict__ pool) {
    const int RV = D3P / 4;
    int i = blockIdx.x * blockDim.x + threadIdx.x;
    if (i >= NNODE * RV) return;
    int n = i / RV, j = i - n * RV;
    red_v4(&pool[batch[n] * RV + j], aggr[i]);
}
__global__ void pool_cnt(const int* __restrict__ batch, float* __restrict__ cnt) {
    int n = blockIdx.x * blockDim.x + threadIdx.x;
    if (n < NNODE) atomicAdd(&cnt[batch[n]], 1.f);
}
__global__ void head_kernel(const float* __restrict__ pool, const float* __restrict__ cnt,
                            const float* __restrict__ wp, const float* __restrict__ bp,
                            float* __restrict__ out) {
    __shared__ float gm[OUT3];
    int b = blockIdx.x;
    float inv = 1.f / fmaxf(cnt[b], 1.f);
    for (int o = threadIdx.x; o < OUT3; o += blockDim.x) {
        float s = 0.f;
#pragma unroll
        for (int h = 0; h < H3; h++) s += pool[b * D3P + h * 128 + o];
        gm[o] = s * inv * (1.f / H3);
    }
    __syncthreads();
    if (threadIdx.x < NCLS) {
        float acc = bp[threadIdx.x];
        for (int o = 0; o < OUT3; o++) acc += gm[o] * wp[o * NCLS + threadIdx.x];
        out[b * NCLS + threadIdx.x] = acc;
    }
}

// ---------------- host orchestration ----------------------------------------
extern "C" void kernel_launch(void* const* d_in, const int* in_sizes, int n_in,
                              void* d_out, int out_size) {
    const int*   x    = (const int*)d_in[0];
    const int*   nd   = (const int*)d_in[1];
    const int*   ei   = (const int*)d_in[2];
    const int*   bat  = (const int*)d_in[3];
    const float* nemb = (const float*)d_in[4];
    const float* demb = (const float*)d_in[5];
    const float* w1   = (const float*)d_in[6];
    const float* as1  = (const float*)d_in[7];
    const float* ad1  = (const float*)d_in[8];
    const float* b1   = (const float*)d_in[9];
    const float* w2   = (const float*)d_in[10];
    const float* as2  = (const float*)d_in[11];
    const float* ad2  = (const float*)d_in[12];
    const float* b2   = (const float*)d_in[13];
    const float* w3   = (const float*)d_in[14];
    const float* as3  = (const float*)d_in[15];
    const float* ad3  = (const float*)d_in[16];
    const float* b3   = (const float*)d_in[17];
    const float* wp   = (const float*)d_in[18];
    const float* bp   = (const float*)d_in[19];
    float* out = (float*)d_out;

    float *feat, *proj, *aggr, *es, *ed, *w3p, *b3p, *pool, *cnt;
    int *deg, *off, *cur, *csrc;
    cudaGetSymbolAddress((void**)&feat, g_feat);
    cudaGetSymbolAddress((void**)&proj, g_proj);
    cudaGetSymbolAddress((void**)&aggr, g_aggr);
    cudaGetSymbolAddress((void**)&es,   g_es);
    cudaGetSymbolAddress((void**)&ed,   g_ed);
    cudaGetSymbolAddress((void**)&w3p,  g_w3p);
    cudaGetSymbolAddress((void**)&b3p,  g_b3p);
    cudaGetSymbolAddress((void**)&pool, g_pool);
    cudaGetSymbolAddress((void**)&cnt,  g_cnt);
    cudaGetSymbolAddress((void**)&deg,  g_deg);
    cudaGetSymbolAddress((void**)&off,  g_off);
    cudaGetSymbolAddress((void**)&cur,  g_cur);
    cudaGetSymbolAddress((void**)&csrc, g_csrc);

    const int TB = 256;
    const int eb = (ETOT + TB - 1) / TB;
    const int nb = (NNODE * 32 + TB - 1) / TB;   // warp per node

    node_enc<<<(NNODE * EMB + TB - 1) / TB, TB>>>(x, nd, nemb, demb, feat);
    pad_w3<<<(D1 * D3P + TB - 1) / TB, TB>>>(w3, b3, w3p, b3p);

    // CSR by destination (shared by all 3 layers)
    cudaMemsetAsync(deg, 0, NNODE * 4);
    cudaMemsetAsync(cur, 0, NNODE * 4);
    count_deg<<<eb, TB>>>(ei, deg);
    scan_deg<<<1, 1024>>>(deg, off);
    scatter_edges<<<eb, TB>>>(ei, off, cur, csrc);

    // ---- layer 1: K=64 -> Dout=256, H=4, D=64 ----
    {
        dim3 g(D1 / 128, (NNODE + 127) / 128);
        gemm_tf32<<<g, 256>>>(feat, w1, proj, NNODE, EMB, D1);
        attn_coef<H12, EMB, D1, EMB><<<(NNODE * H12 * 32 + TB - 1) / TB, TB>>>(proj, as1, ad1, es, ed);
        gat_agg<H12, 16, 2><<<nb, TB>>>(off, csrc, es, ed, (const float4*)proj,
                                        (const float4*)b1, (float4*)feat, 1);
    }
    // ---- layer 2: K=256 -> Dout=256 ----
    {
        dim3 g(D1 / 128, (NNODE + 127) / 128);
        gemm_tf32<<<g, 256>>>(feat, w2, proj, NNODE, D1, D1);
        attn_coef<H12, EMB, D1, EMB><<<(NNODE * H12 * 32 + TB - 1) / TB, TB>>>(proj, as2, ad2, es, ed);
        gat_agg<H12, 16, 2><<<nb, TB>>>(off, csrc, es, ed, (const float4*)proj,
                                        (const float4*)b2, (float4*)feat, 1);
    }
    // ---- layer 3 (padded): K=256 -> Dout=768 (head stride 128), H=6 ----
    {
        dim3 g(D3P / 128, (NNODE + 127) / 128);
        gemm_tf32<<<g, 256>>>(feat, w3p, proj, NNODE, D1, D3P);
        attn_coef<H3, OUT3, D3P, 128><<<(NNODE * H3 * 32 + TB - 1) / TB, TB>>>(proj, as3, ad3, es, ed);
        gat_agg<H3, 32, 6><<<nb, TB>>>(off, csrc, es, ed, (const float4*)proj,
                                       (const float4*)b3p, (float4*)aggr, 0);
    }

    // ---- pooling + classifier head ----
    cudaMemsetAsync(pool, 0, NB * D3P * 4);
    cudaMemsetAsync(cnt, 0, NB * 4);
    pool_feat_v4<<<(NNODE * (D3P / 4) + TB - 1) / TB, TB>>>((const float4*)aggr, bat, (float4*)pool);
    pool_cnt<<<(NNODE + TB - 1) / TB, TB>>>(bat, cnt);
    head_kernel<<<NB, 128>>>(pool, cnt, wp, bp, out);
}

// round 5
// speedup vs baseline: 2.6388x; 1.1012x over previous
#include <cuda_runtime.h>
#include <math.h>

#define NNODE 30000
#define NEDGE 300000
#define ETOT  330000
#define NB    300
#define EMB   64
#define D1    256
#define H12   4
#define H3    6
#define OUT3  121
#define D3    726
#define D3P   768
#define NCLS  10

// ---------------- scratch ----------------------------------------------------
__device__ float g_x0  [NNODE * EMB];       // encoder output
__device__ float g_feat[NNODE * D1];        // layer outputs (1,2)
__device__ float g_proj[NNODE * D1];        // layer1 agg-x / layer2 proj
__device__ float g_agg3[NNODE * (H3 * D1)]; // layer3 aggregated x  [N,6,256]
__device__ float g_aggr[NNODE * D3P];       // layer3 output
__device__ float g_es  [NNODE * H3];
__device__ float g_ed  [NNODE * H3];
__device__ float g_va1[EMB * H12], g_vd1[EMB * H12];
__device__ float g_va2[D1 * H12],  g_vd2[D1 * H12];
__device__ float g_va3[D1 * H3],   g_vd3[D1 * H3];
__device__ float g_w3ph[H3 * D1 * 128];     // per-head padded w3 [6][256][128]
__device__ float g_b3p [D3P];
__device__ float g_pool[NB * D3P];
__device__ float g_cnt [NB];
__device__ int   g_deg [NNODE];
__device__ int   g_off [NNODE + 1];
__device__ int   g_cur [NNODE];
__device__ int   g_csrc[ETOT];
__device__ int   g_bsum[32];
__device__ int   g_bpre[32];

__device__ __forceinline__ unsigned f2tf(float x) {
    unsigned r;
    asm("cvt.rna.tf32.f32 %0, %1;" : "=r"(r) : "f"(x));
    return r;
}
__device__ __forceinline__ void red_v4(float4* addr, float4 v) {
    asm volatile("red.global.add.v4.f32 [%0], {%1,%2,%3,%4};" ::
                 "l"(addr), "f"(v.x), "f"(v.y), "f"(v.z), "f"(v.w) : "memory");
}

// ---------------- node encoder ----------------------------------------------
__global__ void node_enc(const int* __restrict__ x, const int* __restrict__ nd,
                         const float* __restrict__ ne, const float* __restrict__ de,
                         float* __restrict__ out) {
    int i = blockIdx.x * blockDim.x + threadIdx.x;
    if (i >= NNODE * EMB) return;
    int n = i >> 6, d = i & 63;
    out[i] = ne[x[n] * EMB + d] + de[nd[n] * EMB + d];
}

// ---------------- prep: per-head padded w3, b3p, attention vectors ----------
__global__ void pad_w3h(const float* __restrict__ w3, const float* __restrict__ b3,
                        float* __restrict__ w3ph, float* __restrict__ b3p) {
    int i = blockIdx.x * blockDim.x + threadIdx.x;
    if (i < H3 * D1 * 128) {
        int h = i >> 15, rem = i & 32767;
        int k = rem >> 7, o = rem & 127;
        w3ph[i] = (o < OUT3) ? w3[k * D3 + h * OUT3 + o] : 0.f;
    }
    if (i < D3P) {
        int h = i >> 7, o = i & 127;
        b3p[i] = (o < OUT3) ? b3[h * OUT3 + o] : 0.f;
    }
}

// va[k*H+h] = sum_d W[k, h*D+d] * a[h*D+d]
__global__ void make_va(const float* __restrict__ w1, const float* __restrict__ as1, const float* __restrict__ ad1,
                        const float* __restrict__ w2, const float* __restrict__ as2, const float* __restrict__ ad2,
                        const float* __restrict__ w3, const float* __restrict__ as3, const float* __restrict__ ad3,
                        float* __restrict__ va1, float* __restrict__ vd1,
                        float* __restrict__ va2, float* __restrict__ vd2,
                        float* __restrict__ va3, float* __restrict__ vd3) {
    int gid = blockIdx.x * blockDim.x + threadIdx.x;
    if (gid < EMB * H12) {
        int k = gid / H12, h = gid - k * H12;
        float s1 = 0.f, s2 = 0.f;
        for (int d = 0; d < EMB; d++) {
            float w = w1[k * D1 + h * EMB + d];
            s1 += w * as1[h * EMB + d];
            s2 += w * ad1[h * EMB + d];
        }
        va1[gid] = s1; vd1[gid] = s2;
        return;
    }
    gid -= EMB * H12;
    if (gid < D1 * H12) {
        int k = gid / H12, h = gid - k * H12;
        float s1 = 0.f, s2 = 0.f;
        for (int d = 0; d < EMB; d++) {
            float w = w2[k * D1 + h * EMB + d];
            s1 += w * as2[h * EMB + d];
            s2 += w * ad2[h * EMB + d];
        }
        va2[gid] = s1; vd2[gid] = s2;
        return;
    }
    gid -= D1 * H12;
    if (gid < D1 * H3) {
        int k = gid / H3, h = gid - k * H3;
        float s1 = 0.f, s2 = 0.f;
        for (int o = 0; o < OUT3; o++) {
            float w = w3[k * D3 + h * OUT3 + o];
            s1 += w * as3[h * OUT3 + o];
            s2 += w * ad3[h * OUT3 + o];
        }
        va3[gid] = s1; vd3[gid] = s2;
    }
}

// ---------------- CSR build (coalesced 3-kernel scan) ------------------------
__global__ void count_deg(const int* __restrict__ ei, int* __restrict__ deg) {
    int e = blockIdx.x * blockDim.x + threadIdx.x;
    if (e >= ETOT) return;
    int d = (e < NEDGE) ? ei[NEDGE + e] : e - NEDGE;
    atomicAdd(&deg[d], 1);
}
__global__ __launch_bounds__(1024) void deg_part(const int* __restrict__ deg,
                                                 int* __restrict__ bsum) {
    __shared__ int ws[32];
    int t = threadIdx.x, lane = t & 31, w = t >> 5;
    int idx = blockIdx.x * 1024 + t;
    int v = (idx < NNODE) ? deg[idx] : 0;
#pragma unroll
    for (int o = 16; o; o >>= 1) v += __shfl_xor_sync(0xffffffffu, v, o);
    if (lane == 0) ws[w] = v;
    __syncthreads();
    if (t < 32) {
        int s = ws[t];
#pragma unroll
        for (int o = 16; o; o >>= 1) s += __shfl_xor_sync(0xffffffffu, s, o);
        if (t == 0) bsum[blockIdx.x] = s;
    }
}
__global__ void scan_bsum(const int* __restrict__ bsum, int* __restrict__ bpre,
                          int* __restrict__ off, int nblk) {
    int t = threadIdx.x;
    int v = (t < nblk) ? bsum[t] : 0;
    int own = v;
#pragma unroll
    for (int o = 1; o < 32; o <<= 1) {
        int y = __shfl_up_sync(0xffffffffu, v, o);
        if (t >= o) v += y;
    }
    if (t < nblk) bpre[t] = v - own;
    if (t == 31) off[NNODE] = v;
}
__global__ __launch_bounds__(1024) void deg_scan(const int* __restrict__ deg,
                                                 const int* __restrict__ bpre,
                                                 int* __restrict__ off) {
    __shared__ int ws[32];
    int t = threadIdx.x, lane = t & 31, w = t >> 5;
    int idx = blockIdx.x * 1024 + t;
    int v = (idx < NNODE) ? deg[idx] : 0;
    int x = v;
#pragma unroll
    for (int o = 1; o < 32; o <<= 1) {
        int y = __shfl_up_sync(0xffffffffu, x, o);
        if (lane >= o) x += y;
    }
    if (lane == 31) ws[w] = x;
    __syncthreads();
    if (w == 0) {
        int y = ws[lane];
#pragma unroll
        for (int o = 1; o < 32; o <<= 1) {
            int z = __shfl_up_sync(0xffffffffu, y, o);
            if (lane >= o) y += z;
        }
        ws[lane] = y;
    }
    __syncthreads();
    int excl = x - v + (w ? ws[w - 1] : 0) + bpre[blockIdx.x];
    if (idx < NNODE) off[idx] = excl;
}
__global__ void scatter_edges(const int* __restrict__ ei, const int* __restrict__ off,
                              int* __restrict__ cur, int* __restrict__ csrc) {
    int e = blockIdx.x * blockDim.x + threadIdx.x;
    if (e >= ETOT) return;
    int s, d;
    if (e < NEDGE) { s = ei[e]; d = ei[NEDGE + e]; }
    else           { s = d = e - NEDGE; }
    int slot = off[d] + atomicAdd(&cur[d], 1);
    csrc[slot] = s;
}

// ---------------- tf32 GEMM, head-batched, fused bias/ELU --------------------
// BM=128, BK=32, 256 threads; BN template (128: warp 32x64; 64: warp 32x32)
template <int BN>
__global__ __launch_bounds__(256) void gemm_tf32(
        const float* __restrict__ A, const float* __restrict__ B,
        float* __restrict__ C, const float* __restrict__ bias,
        int M, int K, int lda, int ldb, int ldc,
        int aHS, int bHS, int cHS, int biasHS, int elu) {
    constexpr int BSTR = BN + 8;
    constexpr int WN = BN / 2;
    constexpr int JT = WN / 8;
    __shared__ unsigned As[128 * 36];
    __shared__ unsigned Bs[32 * BSTR];
    int t = threadIdx.x;
    int warp = t >> 5, lane = t & 31;
    int tg = lane >> 2, t4 = lane & 3;
    int bm = blockIdx.y * 128, bn = blockIdx.x * BN;
    int z = blockIdx.z;
    const float* Az = A + (size_t)aHS * z;
    const float* Bz = B + (size_t)bHS * z;
    float* Cz = C + (size_t)cHS * z;
    int wm = (warp & 3) * 32, wn = (warp >> 2) * WN;
    float c[2][JT][4];
#pragma unroll
    for (int i = 0; i < 2; i++)
#pragma unroll
        for (int j = 0; j < JT; j++)
#pragma unroll
            for (int q = 0; q < 4; q++) c[i][j][q] = 0.f;

    for (int k0 = 0; k0 < K; k0 += 32) {
#pragma unroll
        for (int i = 0; i < 4; i++) {
            int v = t + 256 * i;
            int row = v >> 3, c4 = (v & 7) << 2;
            float4 f = make_float4(0.f, 0.f, 0.f, 0.f);
            int gr = bm + row;
            if (gr < M) f = *(const float4*)(Az + (size_t)gr * lda + k0 + c4);
            uint4 u = make_uint4(f2tf(f.x), f2tf(f.y), f2tf(f.z), f2tf(f.w));
            *(uint4*)(As + row * 36 + c4) = u;
        }
#pragma unroll
        for (int i = 0; i < BN / 32; i++) {
            int v = t + 256 * i;
            int row = v / (BN / 4), c4 = (v % (BN / 4)) * 4;
            float4 f = *(const float4*)(Bz + (size_t)(k0 + row) * ldb + bn + c4);
            uint4 u = make_uint4(f2tf(f.x), f2tf(f.y), f2tf(f.z), f2tf(f.w));
            *(uint4*)(Bs + row * BSTR + c4) = u;
        }
        __syncthreads();
#pragma unroll
        for (int ks = 0; ks < 4; ks++) {
            unsigned a[2][4], b[JT][2];
#pragma unroll
            for (int i = 0; i < 2; i++) {
                int r = wm + 16 * i + tg;
                int kc = ks * 8 + t4;
                a[i][0] = As[r * 36 + kc];
                a[i][1] = As[(r + 8) * 36 + kc];
                a[i][2] = As[r * 36 + kc + 4];
                a[i][3] = As[(r + 8) * 36 + kc + 4];
            }
#pragma unroll
            for (int j = 0; j < JT; j++) {
                int cc = wn + 8 * j + tg;
                b[j][0] = Bs[(ks * 8 + t4) * BSTR + cc];
                b[j][1] = Bs[(ks * 8 + t4 + 4) * BSTR + cc];
            }
#pragma unroll
            for (int i = 0; i < 2; i++)
#pragma unroll
                for (int j = 0; j < JT; j++) {
                    asm volatile(
                        "mma.sync.aligned.m16n8k8.row.col.f32.tf32.tf32.f32 "
                        "{%0,%1,%2,%3}, {%4,%5,%6,%7}, {%8,%9}, {%0,%1,%2,%3};"
                        : "+f"(c[i][j][0]), "+f"(c[i][j][1]),
                          "+f"(c[i][j][2]), "+f"(c[i][j][3])
                        : "r"(a[i][0]), "r"(a[i][1]), "r"(a[i][2]), "r"(a[i][3]),
                          "r"(b[j][0]), "r"(b[j][1]));
                }
        }
        __syncthreads();
    }
#pragma unroll
    for (int i = 0; i < 2; i++)
#pragma unroll
        for (int j = 0; j < JT; j++) {
            int r = bm + wm + 16 * i + tg;
            int cc = bn + wn + 8 * j + t4 * 2;
            float v0 = c[i][j][0], v1 = c[i][j][1];
            float v2 = c[i][j][2], v3 = c[i][j][3];
            if (bias) {
                float b0 = bias[biasHS * z + cc], b1 = bias[biasHS * z + cc + 1];
                v0 += b0; v1 += b1; v2 += b0; v3 += b1;
            }
            if (elu) {
                v0 = v0 > 0.f ? v0 : expm1f(v0);
                v1 = v1 > 0.f ? v1 : expm1f(v1);
                v2 = v2 > 0.f ? v2 : expm1f(v2);
                v3 = v3 > 0.f ? v3 : expm1f(v3);
            }
            if (r < M)     *(float2*)(Cz + (size_t)r * ldc + cc)       = make_float2(v0, v1);
            if (r + 8 < M) *(float2*)(Cz + (size_t)(r + 8) * ldc + cc) = make_float2(v2, v3);
        }
}

// ---------------- es/ed from input features: [N,K] @ va/vd [K,H] -------------
template <int K, int H>
__global__ __launch_bounds__(256) void attn_small(const float* __restrict__ feat,
                                                  const float* __restrict__ va,
                                                  const float* __restrict__ vd,
                                                  float* __restrict__ es,
                                                  float* __restrict__ ed) {
    __shared__ float sva[K * H], svd[K * H];
    int t = threadIdx.x;
    for (int i = t; i < K * H; i += 256) { sva[i] = va[i]; svd[i] = vd[i]; }
    __syncthreads();
    int gw = blockIdx.x * 8 + (t >> 5);
    int lane = t & 31;
    if (gw >= NNODE) return;
    const float* row = feat + (size_t)gw * K;
    float e1[H], e2[H];
#pragma unroll
    for (int h = 0; h < H; h++) { e1[h] = 0.f; e2[h] = 0.f; }
    for (int k = lane; k < K; k += 32) {
        float xv = row[k];
#pragma unroll
        for (int h = 0; h < H; h++) {
            e1[h] += xv * sva[k * H + h];
            e2[h] += xv * svd[k * H + h];
        }
    }
#pragma unroll
    for (int h = 0; h < H; h++)
#pragma unroll
        for (int o = 16; o; o >>= 1) {
            e1[h] += __shfl_xor_sync(0xffffffffu, e1[h], o);
            e2[h] += __shfl_xor_sync(0xffffffffu, e2[h], o);
        }
    if (lane == 0)
#pragma unroll
        for (int h = 0; h < H; h++) {
            es[gw * H + h] = e1[h];
            ed[gw * H + h] = e2[h];
        }
}

// ---------------- aggregate input x with per-head alpha (layers 1 & 3) ------
template <int H, int K4>
__global__ __launch_bounds__(256) void gat_agg_x(const int* __restrict__ off,
                                                 const int* __restrict__ csrc,
                                                 const float* __restrict__ es,
                                                 const float* __restrict__ ed,
                                                 const float4* __restrict__ xin,
                                                 float4* __restrict__ agg) {
    constexpr int K4PL = (K4 + 31) / 32;
    int gw = (blockIdx.x * blockDim.x + threadIdx.x) >> 5;
    int lane = threadIdx.x & 31;
    if (gw >= NNODE) return;
    int o0 = off[gw], o1 = off[gw + 1];
    float edv[H], m[H], sm[H];
#pragma unroll
    for (int h = 0; h < H; h++) {
        edv[h] = __ldg(&ed[gw * H + h]);
        m[h] = -1e30f; sm[h] = 0.f;
    }
    for (int i = o0 + lane; i < o1; i += 32) {
        int s = __ldg(&csrc[i]);
#pragma unroll
        for (int h = 0; h < H; h++) {
            float v = __ldg(&es[s * H + h]) + edv[h];
            v = v > 0.f ? v : 0.2f * v;
            m[h] = fmaxf(m[h], v);
        }
    }
#pragma unroll
    for (int h = 0; h < H; h++)
#pragma unroll
        for (int o = 16; o; o >>= 1)
            m[h] = fmaxf(m[h], __shfl_xor_sync(0xffffffffu, m[h], o));
    for (int i = o0 + lane; i < o1; i += 32) {
        int s = __ldg(&csrc[i]);
#pragma unroll
        for (int h = 0; h < H; h++) {
            float v = __ldg(&es[s * H + h]) + edv[h];
            v = v > 0.f ? v : 0.2f * v;
            sm[h] += __expf(v - m[h]);
        }
    }
#pragma unroll
    for (int h = 0; h < H; h++) {
#pragma unroll
        for (int o = 16; o; o >>= 1)
            sm[h] += __shfl_xor_sync(0xffffffffu, sm[h], o);
        sm[h] = 1.f / (sm[h] + 1e-16f);
    }
    float4 acc[H][K4PL];
#pragma unroll
    for (int h = 0; h < H; h++)
#pragma unroll
        for (int tt = 0; tt < K4PL; tt++) acc[h][tt] = make_float4(0.f, 0.f, 0.f, 0.f);
    for (int i = o0; i < o1; i++) {
        int s = __ldg(&csrc[i]);
        float alpha = 0.f;
        if (lane < H) {
            float v = __ldg(&es[s * H + lane]) + edv[lane];
            v = v > 0.f ? v : 0.2f * v;
            alpha = __expf(v - m[lane]) * sm[lane];
        }
        const float4* prow = xin + (size_t)s * K4;
        float4 p[K4PL];
#pragma unroll
        for (int tt = 0; tt < K4PL; tt++) {
            int k4 = lane + 32 * tt;
            p[tt] = (k4 < K4) ? __ldg(&prow[k4]) : make_float4(0.f, 0.f, 0.f, 0.f);
        }
#pragma unroll
        for (int h = 0; h < H; h++) {
            float a = __shfl_sync(0xffffffffu, alpha, h);
#pragma unroll
            for (int tt = 0; tt < K4PL; tt++) {
                acc[h][tt].x += a * p[tt].x;
                acc[h][tt].y += a * p[tt].y;
                acc[h][tt].z += a * p[tt].z;
                acc[h][tt].w += a * p[tt].w;
            }
        }
    }
    float4* orow = agg + (size_t)gw * (H * K4);
#pragma unroll
    for (int h = 0; h < H; h++)
#pragma unroll
        for (int tt = 0; tt < K4PL; tt++) {
            int k4 = lane + 32 * tt;
            if (k4 < K4) orow[h * K4 + k4] = acc[h][tt];
        }
}

// ---------------- layer-2 aggregation of projected features -----------------
template <int H, int HSTR4, int FPL>
__global__ __launch_bounds__(256) void gat_agg(const int* __restrict__ off,
                                               const int* __restrict__ csrc,
                                               const float* __restrict__ es,
                                               const float* __restrict__ ed,
                                               const float4* __restrict__ proj,
                                               const float4* __restrict__ bias,
                                               float4* __restrict__ outp, int elu) {
    const int NV4 = H * HSTR4;
    int gw = (blockIdx.x * blockDim.x + threadIdx.x) >> 5;
    int lane = threadIdx.x & 31;
    if (gw >= NNODE) return;
    int o0 = off[gw], o1 = off[gw + 1];
    float edv[H], m[H], sm[H];
#pragma unroll
    for (int h = 0; h < H; h++) {
        edv[h] = __ldg(&ed[gw * H + h]);
        m[h] = -1e30f; sm[h] = 0.f;
    }
    for (int i = o0 + lane; i < o1; i += 32) {
        int s = __ldg(&csrc[i]);
#pragma unroll
        for (int h = 0; h < H; h++) {
            float v = __ldg(&es[s * H + h]) + edv[h];
            v = v > 0.f ? v : 0.2f * v;
            m[h] = fmaxf(m[h], v);
        }
    }
#pragma unroll
    for (int h = 0; h < H; h++)
#pragma unroll
        for (int o = 16; o; o >>= 1)
            m[h] = fmaxf(m[h], __shfl_xor_sync(0xffffffffu, m[h], o));
    for (int i = o0 + lane; i < o1; i += 32) {
        int s = __ldg(&csrc[i]);
#pragma unroll
        for (int h = 0; h < H; h++) {
            float v = __ldg(&es[s * H + h]) + edv[h];
            v = v > 0.f ? v : 0.2f * v;
            sm[h] += __expf(v - m[h]);
        }
    }
#pragma unroll
    for (int h = 0; h < H; h++) {
#pragma unroll
        for (int o = 16; o; o >>= 1)
            sm[h] += __shfl_xor_sync(0xffffffffu, sm[h], o);
        sm[h] = 1.f / (sm[h] + 1e-16f);
    }
    float4 acc[FPL];
#pragma unroll
    for (int tt = 0; tt < FPL; tt++) acc[tt] = make_float4(0.f, 0.f, 0.f, 0.f);
    for (int i = o0; i < o1; i++) {
        int s = __ldg(&csrc[i]);
        float alpha = 0.f;
        if (lane < H) {
            float v = __ldg(&es[s * H + lane]) + edv[lane];
            v = v > 0.f ? v : 0.2f * v;
            alpha = __expf(v - m[lane]) * sm[lane];
        }
        const float4* prow = proj + (size_t)s * NV4;
#pragma unroll
        for (int tt = 0; tt < FPL; tt++) {
            int j4 = lane + 32 * tt;
            float a = __shfl_sync(0xffffffffu, alpha, j4 / HSTR4);
            float4 p = __ldg(&prow[j4]);
            acc[tt].x += p.x * a;
            acc[tt].y += p.y * a;
            acc[tt].z += p.z * a;
            acc[tt].w += p.w * a;
        }
    }
    float4* orow = outp + (size_t)gw * NV4;
#pragma unroll
    for (int tt = 0; tt < FPL; tt++) {
        int j4 = lane + 32 * tt;
        float4 b = __ldg(&bias[j4]);
        float4 v = acc[tt];
        v.x += b.x; v.y += b.y; v.z += b.z; v.w += b.w;
        if (elu) {
            v.x = v.x > 0.f ? v.x : expm1f(v.x);
            v.y = v.y > 0.f ? v.y : expm1f(v.y);
            v.z = v.z > 0.f ? v.z : expm1f(v.z);
            v.w = v.w > 0.f ? v.w : expm1f(v.w);
        }
        orow[j4] = v;
    }
}

// ---------------- pooling + head --------------------------------------------
__global__ void pool_feat_v4(const float4* __restrict__ aggr, const int* __restrict__ batch,
                             float4* __restrict__ pool) {
    const int RV = D3P / 4;
    int i = blockIdx.x * blockDim.x + threadIdx.x;
    if (i >= NNODE * RV) return;
    int n = i / RV, j = i - n * RV;
    red_v4(&pool[batch[n] * RV + j], aggr[i]);
}
__global__ void pool_cnt(const int* __restrict__ batch, float* __restrict__ cnt) {
    int n = blockIdx.x * blockDim.x + threadIdx.x;
    if (n < NNODE) atomicAdd(&cnt[batch[n]], 1.f);
}
__global__ void head_kernel(const float* __restrict__ pool, const float* __restrict__ cnt,
                            const float* __restrict__ wp, const float* __restrict__ bp,
                            float* __restrict__ out) {
    __shared__ float gm[OUT3];
    int b = blockIdx.x;
    float inv = 1.f / fmaxf(cnt[b], 1.f);
    for (int o = threadIdx.x; o < OUT3; o += blockDim.x) {
        float s = 0.f;
#pragma unroll
        for (int h = 0; h < H3; h++) s += pool[b * D3P + h * 128 + o];
        gm[o] = s * inv * (1.f / H3);
    }
    __syncthreads();
    if (threadIdx.x < NCLS) {
        float acc = bp[threadIdx.x];
        for (int o = 0; o < OUT3; o++) acc += gm[o] * wp[o * NCLS + threadIdx.x];
        out[b * NCLS + threadIdx.x] = acc;
    }
}

// ---------------- host orchestration ----------------------------------------
extern "C" void kernel_launch(void* const* d_in, const int* in_sizes, int n_in,
                              void* d_out, int out_size) {
    const int*   x    = (const int*)d_in[0];
    const int*   nd   = (const int*)d_in[1];
    const int*   ei   = (const int*)d_in[2];
    const int*   bat  = (const int*)d_in[3];
    const float* nemb = (const float*)d_in[4];
    const float* demb = (const float*)d_in[5];
    const float* w1   = (const float*)d_in[6];
    const float* as1  = (const float*)d_in[7];
    const float* ad1  = (const float*)d_in[8];
    const float* b1   = (const float*)d_in[9];
    const float* w2   = (const float*)d_in[10];
    const float* as2  = (const float*)d_in[11];
    const float* ad2  = (const float*)d_in[12];
    const float* b2   = (const float*)d_in[13];
    const float* w3   = (const float*)d_in[14];
    const float* as3  = (const float*)d_in[15];
    const float* ad3  = (const float*)d_in[16];
    const float* b3   = (const float*)d_in[17];
    const float* wp   = (const float*)d_in[18];
    const float* bp   = (const float*)d_in[19];
    float* out = (float*)d_out;

    float *x0, *feat, *proj, *agg3, *aggr, *es, *ed;
    float *va1, *vd1, *va2, *vd2, *va3, *vd3, *w3ph, *b3p, *pool, *cnt;
    int *deg, *off, *cur, *csrc, *bsum, *bpre;
    cudaGetSymbolAddress((void**)&x0,   g_x0);
    cudaGetSymbolAddress((void**)&feat, g_feat);
    cudaGetSymbolAddress((void**)&proj, g_proj);
    cudaGetSymbolAddress((void**)&agg3, g_agg3);
    cudaGetSymbolAddress((void**)&aggr, g_aggr);
    cudaGetSymbolAddress((void**)&es,   g_es);
    cudaGetSymbolAddress((void**)&ed,   g_ed);
    cudaGetSymbolAddress((void**)&va1,  g_va1);
    cudaGetSymbolAddress((void**)&vd1,  g_vd1);
    cudaGetSymbolAddress((void**)&va2,  g_va2);
    cudaGetSymbolAddress((void**)&vd2,  g_vd2);
    cudaGetSymbolAddress((void**)&va3,  g_va3);
    cudaGetSymbolAddress((void**)&vd3,  g_vd3);
    cudaGetSymbolAddress((void**)&w3ph, g_w3ph);
    cudaGetSymbolAddress((void**)&b3p,  g_b3p);
    cudaGetSymbolAddress((void**)&pool, g_pool);
    cudaGetSymbolAddress((void**)&cnt,  g_cnt);
    cudaGetSymbolAddress((void**)&deg,  g_deg);
    cudaGetSymbolAddress((void**)&off,  g_off);
    cudaGetSymbolAddress((void**)&cur,  g_cur);
    cudaGetSymbolAddress((void**)&csrc, g_csrc);
    cudaGetSymbolAddress((void**)&bsum, g_bsum);
    cudaGetSymbolAddress((void**)&bpre, g_bpre);

    const int TB = 256;
    const int eb = (ETOT + TB - 1) / TB;
    const int nb = (NNODE * 32 + TB - 1) / TB;
    const int ab = (NNODE + 7) / 8;
    const int SB = (NNODE + 1023) / 1024;   // 30 scan blocks

    node_enc<<<(NNODE * EMB + TB - 1) / TB, TB>>>(x, nd, nemb, demb, x0);
    pad_w3h<<<(H3 * D1 * 128 + TB - 1) / TB, TB>>>(w3, b3, w3ph, b3p);
    make_va<<<(EMB * H12 + D1 * H12 + D1 * H3 + TB - 1) / TB, TB>>>(
        w1, as1, ad1, w2, as2, ad2, w3, as3, ad3, va1, vd1, va2, vd2, va3, vd3);

    // CSR by destination
    cudaMemsetAsync(deg, 0, NNODE * 4);
    cudaMemsetAsync(cur, 0, NNODE * 4);
    count_deg<<<eb, TB>>>(ei, deg);
    deg_part<<<SB, 1024>>>(deg, bsum);
    scan_bsum<<<1, 32>>>(bsum, bpre, off, SB);
    deg_scan<<<SB, 1024>>>(deg, bpre, off);
    scatter_edges<<<eb, TB>>>(ei, off, cur, csrc);

    // ---- layer 1: aggregate x (K=64), then per-head GEMM [N,64]@[64,64] ----
    attn_small<EMB, H12><<<ab, TB>>>(x0, va1, vd1, es, ed);
    gat_agg_x<H12, 16><<<nb, TB>>>(off, csrc, es, ed, (const float4*)x0, (float4*)proj);
    {
        dim3 g(1, (NNODE + 127) / 128, H12);
        gemm_tf32<64><<<g, 256>>>(proj, w1, feat, b1, NNODE, EMB,
                                  D1, D1, D1, EMB, EMB, EMB, EMB, 1);
    }

    // ---- layer 2: proj = feat@w2, aggregate proj (Dout = K = 256) ----
    {
        dim3 g(2, (NNODE + 127) / 128, 1);
        gemm_tf32<128><<<g, 256>>>(feat, w2, proj, nullptr, NNODE, D1,
                                   D1, D1, D1, 0, 0, 0, 0, 0);
    }
    attn_small<D1, H12><<<ab, TB>>>(feat, va2, vd2, es, ed);
    gat_agg<H12, 16, 2><<<nb, TB>>>(off, csrc, es, ed, (const float4*)proj,
                                    (const float4*)b2, (float4*)feat, 1);

    // ---- layer 3: aggregate x (K=256) per 6 heads, then per-head GEMM ------
    attn_small<D1, H3><<<ab, TB>>>(feat, va3, vd3, es, ed);
    gat_agg_x<H3, 64><<<nb, TB>>>(off, csrc, es, ed, (const float4*)feat, (float4*)agg3);
    {
        dim3 g(1, (NNODE + 127) / 128, H3);
        gemm_tf32<128><<<g, 256>>>(agg3, w3ph, aggr, b3p, NNODE, D1,
                                   H3 * D1, 128, D3P, D1, D1 * 128, 128, 128, 0);
    }

    // ---- pooling + classifier head ----
    cudaMemsetAsync(pool, 0, NB * D3P * 4);
    cudaMemsetAsync(cnt, 0, NB * 4);
    pool_feat_v4<<<(NNODE * (D3P / 4) + TB - 1) / TB, TB>>>((const float4*)aggr, bat, (float4*)pool);
    pool_cnt<<<(NNODE + TB - 1) / TB, TB>>>(bat, cnt);
    head_kernel<<<NB, 128>>>(pool, cnt, wp, bp, out);
}

// round 7
// speedup vs baseline: 3.2862x; 1.2453x over previous
#include <cuda_runtime.h>
#include <cuda_fp16.h>
#include <math.h>

#define NNODE 30000
#define NEDGE 300000
#define ETOT  330000
#define NB    300
#define EMB   64
#define D1    256
#define H12   4
#define H3    6
#define OUT3  121
#define D3    726
#define D3P   768
#define NCLS  10

// ---------------- scratch ----------------------------------------------------
__device__ float  g_x0   [NNODE * EMB];
__device__ __half g_x0h  [NNODE * EMB];
__device__ __half g_p1h  [NNODE * D1];        // layer1 aggregated x (per-head), fp16
__device__ float  g_feat [NNODE * D1];        // layer1 output fp32
__device__ __half g_feath[NNODE * D1];        // layer1 output fp16
__device__ __half g_projh[NNODE * D1];        // layer2 projection fp16
__device__ float  g_feat2[NNODE * D1];        // layer2 output fp32
__device__ __half g_feat2h[NNODE * D1];       // layer2 output fp16
__device__ __half g_agg3h[NNODE * (H3 * D1)]; // layer3 aggregated x fp16 [N,6,256]
__device__ float  g_aggr [NNODE * D3P];       // layer3 output fp32
__device__ float  g_es  [NNODE * H3];
__device__ float  g_ed  [NNODE * H3];
__device__ float  g_va1[EMB * H12], g_vd1[EMB * H12];
__device__ float  g_va2[D1 * H12],  g_vd2[D1 * H12];
__device__ float  g_va3[D1 * H3],   g_vd3[D1 * H3];
__device__ __half g_w1t[H12 * 64 * 64];       // [h][n][k]
__device__ __half g_w2t[D1 * D1];             // [n][k]
__device__ __half g_w3t[H3 * 128 * D1];       // [h][n(128 pad)][k]
__device__ float  g_b3p[D3P];
__device__ float  g_pool[NB * D3P];
__device__ float  g_cnt [NB];
__device__ int    g_deg [NNODE];
__device__ int    g_off [NNODE + 1];
__device__ int    g_cur [NNODE];
__device__ int    g_csrc[ETOT];
__device__ int    g_bsum[32];
__device__ int    g_bpre[32];

__device__ __forceinline__ void red_v4(float4* addr, float4 v) {
    asm volatile("red.global.add.v4.f32 [%0], {%1,%2,%3,%4};" ::
                 "l"(addr), "f"(v.x), "f"(v.y), "f"(v.z), "f"(v.w) : "memory");
}

// ---------------- node encoder (dual fp32/fp16) ------------------------------
__global__ void node_enc(const int* __restrict__ x, const int* __restrict__ nd,
                         const float* __restrict__ ne, const float* __restrict__ de,
                         float* __restrict__ out, __half* __restrict__ outh) {
    int i = blockIdx.x * blockDim.x + threadIdx.x;
    if (i >= NNODE * EMB) return;
    int n = i >> 6, d = i & 63;
    float v = ne[x[n] * EMB + d] + de[nd[n] * EMB + d];
    out[i] = v;
    outh[i] = __float2half(v);
}

// ---------------- weight prep: fp16 transposed weights + padded b3 ----------
__global__ void prep_weights(const float* __restrict__ w1, const float* __restrict__ w2,
                             const float* __restrict__ w3, const float* __restrict__ b3,
                             __half* __restrict__ w1t, __half* __restrict__ w2t,
                             __half* __restrict__ w3t, float* __restrict__ b3p) {
    int i = blockIdx.x * blockDim.x + threadIdx.x;
    if (i < 16384) {
        int h = i >> 12, r = i & 4095, n = r >> 6, k = r & 63;
        w1t[i] = __float2half(w1[k * D1 + h * 64 + n]);
    }
    int j = i - 16384;
    if (j >= 0 && j < 65536) {
        int n = j >> 8, k = j & 255;
        w2t[j] = __float2half(w2[k * D1 + n]);
    }
    int q = i - (16384 + 65536);
    if (q >= 0 && q < H3 * 128 * D1) {
        int h = q >> 15, r = q & 32767, n = r >> 8, k = r & 255;
        w3t[q] = __float2half(n < OUT3 ? w3[k * D3 + h * OUT3 + n] : 0.f);
    }
    if (i < D3P) {
        int h = i >> 7, o = i & 127;
        b3p[i] = (o < OUT3) ? b3[h * OUT3 + o] : 0.f;
    }
}

// va[k*H+h] = sum_d W[k, h*D+d] * a[h*D+d]
__global__ void make_va(const float* __restrict__ w1, const float* __restrict__ as1, const float* __restrict__ ad1,
                        const float* __restrict__ w2, const float* __restrict__ as2, const float* __restrict__ ad2,
                        const float* __restrict__ w3, const float* __restrict__ as3, const float* __restrict__ ad3,
                        float* __restrict__ va1, float* __restrict__ vd1,
                        float* __restrict__ va2, float* __restrict__ vd2,
                        float* __restrict__ va3, float* __restrict__ vd3) {
    int gid = blockIdx.x * blockDim.x + threadIdx.x;
    if (gid < EMB * H12) {
        int k = gid / H12, h = gid - k * H12;
        float s1 = 0.f, s2 = 0.f;
        for (int d = 0; d < EMB; d++) {
            float w = w1[k * D1 + h * EMB + d];
            s1 += w * as1[h * EMB + d];
            s2 += w * ad1[h * EMB + d];
        }
        va1[gid] = s1; vd1[gid] = s2;
        return;
    }
    gid -= EMB * H12;
    if (gid < D1 * H12) {
        int k = gid / H12, h = gid - k * H12;
        float s1 = 0.f, s2 = 0.f;
        for (int d = 0; d < EMB; d++) {
            float w = w2[k * D1 + h * EMB + d];
            s1 += w * as2[h * EMB + d];
            s2 += w * ad2[h * EMB + d];
        }
        va2[gid] = s1; vd2[gid] = s2;
        return;
    }
    gid -= D1 * H12;
    if (gid < D1 * H3) {
        int k = gid / H3, h = gid - k * H3;
        float s1 = 0.f, s2 = 0.f;
        for (int o = 0; o < OUT3; o++) {
            float w = w3[k * D3 + h * OUT3 + o];
            s1 += w * as3[h * OUT3 + o];
            s2 += w * ad3[h * OUT3 + o];
        }
        va3[gid] = s1; vd3[gid] = s2;
    }
}

// ---------------- CSR build --------------------------------------------------
__global__ void count_deg(const int* __restrict__ ei, int* __restrict__ deg) {
    int e = blockIdx.x * blockDim.x + threadIdx.x;
    if (e >= ETOT) return;
    int d = (e < NEDGE) ? ei[NEDGE + e] : e - NEDGE;
    atomicAdd(&deg[d], 1);
}
__global__ __launch_bounds__(1024) void deg_part(const int* __restrict__ deg,
                                                 int* __restrict__ bsum) {
    __shared__ int ws[32];
    int t = threadIdx.x, lane = t & 31, w = t >> 5;
    int idx = blockIdx.x * 1024 + t;
    int v = (idx < NNODE) ? deg[idx] : 0;
#pragma unroll
    for (int o = 16; o; o >>= 1) v += __shfl_xor_sync(0xffffffffu, v, o);
    if (lane == 0) ws[w] = v;
    __syncthreads();
    if (t < 32) {
        int s = ws[t];
#pragma unroll
        for (int o = 16; o; o >>= 1) s += __shfl_xor_sync(0xffffffffu, s, o);
        if (t == 0) bsum[blockIdx.x] = s;
    }
}
__global__ void scan_bsum(const int* __restrict__ bsum, int* __restrict__ bpre,
                          int* __restrict__ off, int nblk) {
    int t = threadIdx.x;
    int v = (t < nblk) ? bsum[t] : 0;
    int own = v;
#pragma unroll
    for (int o = 1; o < 32; o <<= 1) {
        int y = __shfl_up_sync(0xffffffffu, v, o);
        if (t >= o) v += y;
    }
    if (t < nblk) bpre[t] = v - own;
    if (t == 31) off[NNODE] = v;
}
__global__ __launch_bounds__(1024) void deg_scan(const int* __restrict__ deg,
                                                 const int* __restrict__ bpre,
                                                 int* __restrict__ off) {
    __shared__ int ws[32];
    int t = threadIdx.x, lane = t & 31, w = t >> 5;
    int idx = blockIdx.x * 1024 + t;
    int v = (idx < NNODE) ? deg[idx] : 0;
    int x = v;
#pragma unroll
    for (int o = 1; o < 32; o <<= 1) {
        int y = __shfl_up_sync(0xffffffffu, x, o);
        if (lane >= o) x += y;
    }
    if (lane == 31) ws[w] = x;
    __syncthreads();
    if (w == 0) {
        int y = ws[lane];
#pragma unroll
        for (int o = 1; o < 32; o <<= 1) {
            int z = __shfl_up_sync(0xffffffffu, y, o);
            if (lane >= o) y += z;
        }
        ws[lane] = y;
    }
    __syncthreads();
    int excl = x - v + (w ? ws[w - 1] : 0) + bpre[blockIdx.x];
    if (idx < NNODE) off[idx] = excl;
}
__global__ void scatter_edges(const int* __restrict__ ei, const int* __restrict__ off,
                              int* __restrict__ cur, int* __restrict__ csrc) {
    int e = blockIdx.x * blockDim.x + threadIdx.x;
    if (e >= ETOT) return;
    int s, d;
    if (e < NEDGE) { s = ei[e]; d = ei[NEDGE + e]; }
    else           { s = d = e - NEDGE; }
    int slot = off[d] + atomicAdd(&cur[d], 1);
    csrc[slot] = s;
}

// ---------------- fp16 tensor GEMM: C[M,N] = A[M,K] @ Bt[N,K]^T --------------
// BM=128, BK=32, 256 threads, 8 warps (4x2); BN in {64,128}; mma m16n8k16
template <int BN>
__global__ __launch_bounds__(256) void gemm_h16(
        const __half* __restrict__ A, const __half* __restrict__ Bt,
        float* __restrict__ C, __half* __restrict__ Ch, const float* __restrict__ bias,
        int M, int K, int lda, int ldb, int ldc,
        int aHS, int bHS, int cHS, int biasHS, int elu) {
    constexpr int AST = 40;
    constexpr int WN = BN / 2;
    constexpr int JT = WN / 8;
    __shared__ __half As[128 * AST];
    __shared__ __half Bs[BN * AST];
    int t = threadIdx.x;
    int warp = t >> 5, lane = t & 31;
    int tg = lane >> 2, t4 = lane & 3;
    int bm = blockIdx.y * 128, bn = blockIdx.x * BN;
    int z = blockIdx.z;
    const __half* Az = A + (size_t)aHS * z;
    const __half* Bz = Bt + (size_t)bHS * z;
    int wm = (warp & 3) * 32, wn = (warp >> 2) * WN;
    float c[2][JT][4];
#pragma unroll
    for (int i = 0; i < 2; i++)
#pragma unroll
        for (int j = 0; j < JT; j++)
#pragma unroll
            for (int q = 0; q < 4; q++) c[i][j][q] = 0.f;

    for (int k0 = 0; k0 < K; k0 += 32) {
#pragma unroll
        for (int i = 0; i < 2; i++) {
            int v = t + 256 * i;
            int row = v >> 2, kc = (v & 3) * 8;
            uint4 u = make_uint4(0u, 0u, 0u, 0u);
            int gr = bm + row;
            if (gr < M) u = *(const uint4*)(Az + (size_t)gr * lda + k0 + kc);
            *(uint4*)&As[row * AST + kc] = u;
        }
#pragma unroll
        for (int i = 0; i < BN / 64; i++) {
            int v = t + 256 * i;
            int row = v >> 2, kc = (v & 3) * 8;
            *(uint4*)&Bs[row * AST + kc] =
                *(const uint4*)(Bz + (size_t)(bn + row) * ldb + k0 + kc);
        }
        __syncthreads();
#pragma unroll
        for (int ks = 0; ks < 2; ks++) {
            int kb = ks * 16;
            unsigned a[2][4], b[JT][2];
#pragma unroll
            for (int i = 0; i < 2; i++) {
                int r = wm + 16 * i + tg;
                a[i][0] = *(const unsigned*)&As[r * AST + kb + 2 * t4];
                a[i][1] = *(const unsigned*)&As[(r + 8) * AST + kb + 2 * t4];
                a[i][2] = *(const unsigned*)&As[r * AST + kb + 2 * t4 + 8];
                a[i][3] = *(const unsigned*)&As[(r + 8) * AST + kb + 2 * t4 + 8];
            }
#pragma unroll
            for (int j = 0; j < JT; j++) {
                int n = wn + 8 * j + tg;
                b[j][0] = *(const unsigned*)&Bs[n * AST + kb + 2 * t4];
                b[j][1] = *(const unsigned*)&Bs[n * AST + kb + 2 * t4 + 8];
            }
#pragma unroll
            for (int i = 0; i < 2; i++)
#pragma unroll
                for (int j = 0; j < JT; j++) {
                    asm volatile(
                        "mma.sync.aligned.m16n8k16.row.col.f32.f16.f16.f32 "
                        "{%0,%1,%2,%3}, {%4,%5,%6,%7}, {%8,%9}, {%0,%1,%2,%3};"
                        : "+f"(c[i][j][0]), "+f"(c[i][j][1]),
                          "+f"(c[i][j][2]), "+f"(c[i][j][3])
                        : "r"(a[i][0]), "r"(a[i][1]), "r"(a[i][2]), "r"(a[i][3]),
                          "r"(b[j][0]), "r"(b[j][1]));
                }
        }
        __syncthreads();
    }
#pragma unroll
    for (int i = 0; i < 2; i++)
#pragma unroll
        for (int j = 0; j < JT; j++) {
            int r = bm + wm + 16 * i + tg;
            int cc = bn + wn + 8 * j + 2 * t4;
            float v0 = c[i][j][0], v1 = c[i][j][1];
            float v2 = c[i][j][2], v3 = c[i][j][3];
            if (bias) {
                float b0 = bias[biasHS * z + cc], b1 = bias[biasHS * z + cc + 1];
                v0 += b0; v1 += b1; v2 += b0; v3 += b1;
            }
            if (elu) {
                v0 = v0 > 0.f ? v0 : expm1f(v0);
                v1 = v1 > 0.f ? v1 : expm1f(v1);
                v2 = v2 > 0.f ? v2 : expm1f(v2);
                v3 = v3 > 0.f ? v3 : expm1f(v3);
            }
            if (C) {
                float* Cz = C + (size_t)cHS * z;
                if (r < M)     *(float2*)(Cz + (size_t)r * ldc + cc)       = make_float2(v0, v1);
                if (r + 8 < M) *(float2*)(Cz + (size_t)(r + 8) * ldc + cc) = make_float2(v2, v3);
            }
            if (Ch) {
                __half* Hz = Ch + (size_t)cHS * z;
                if (r < M)     *(__half2*)(Hz + (size_t)r * ldc + cc)       = __floats2half2_rn(v0, v1);
                if (r + 8 < M) *(__half2*)(Hz + (size_t)(r + 8) * ldc + cc) = __floats2half2_rn(v2, v3);
            }
        }
}

// ---------------- es/ed: [N,K] @ va/vd [K,H] (fp32 inputs) -------------------
template <int K, int H>
__global__ __launch_bounds__(256) void attn_small(const float* __restrict__ feat,
                                                  const float* __restrict__ va,
                                                  const float* __restrict__ vd,
                                                  float* __restrict__ es,
                                                  float* __restrict__ ed) {
    __shared__ float sva[K * H], svd[K * H];
    int t = threadIdx.x;
    for (int i = t; i < K * H; i += 256) { sva[i] = va[i]; svd[i] = vd[i]; }
    __syncthreads();
    int gw = blockIdx.x * 8 + (t >> 5);
    int lane = t & 31;
    if (gw >= NNODE) return;
    const float* row = feat + (size_t)gw * K;
    float e1[H], e2[H];
#pragma unroll
    for (int h = 0; h < H; h++) { e1[h] = 0.f; e2[h] = 0.f; }
    for (int k = lane; k < K; k += 32) {
        float xv = row[k];
#pragma unroll
        for (int h = 0; h < H; h++) {
            e1[h] += xv * sva[k * H + h];
            e2[h] += xv * svd[k * H + h];
        }
    }
#pragma unroll
    for (int h = 0; h < H; h++)
#pragma unroll
        for (int o = 16; o; o >>= 1) {
            e1[h] += __shfl_xor_sync(0xffffffffu, e1[h], o);
            e2[h] += __shfl_xor_sync(0xffffffffu, e2[h], o);
        }
    if (lane == 0)
#pragma unroll
        for (int h = 0; h < H; h++) {
            es[gw * H + h] = e1[h];
            ed[gw * H + h] = e2[h];
        }
}

// ---------------- single-pass per-head x aggregation (layers 1 & 3) ---------
// HPL halfs per lane; row width KH = 32*HPL halfs; output [N][H][KH] fp16
template <int H, int HPL>
__global__ __launch_bounds__(256) void gat_agg_xh(const int* __restrict__ off,
                                                  const int* __restrict__ csrc,
                                                  const float* __restrict__ es,
                                                  const float* __restrict__ ed,
                                                  const __half* __restrict__ xin,
                                                  __half* __restrict__ agg) {
    constexpr int KH = 32 * HPL;
    int gw = (blockIdx.x * blockDim.x + threadIdx.x) >> 5;
    int lane = threadIdx.x & 31;
    if (gw >= NNODE) return;
    int o0 = off[gw], o1 = off[gw + 1];
    float edv = (lane < H) ? __ldg(&ed[gw * H + lane]) : 0.f;
    float smv = 0.f;
    float acc[H][HPL];
#pragma unroll
    for (int h = 0; h < H; h++)
#pragma unroll
        for (int p = 0; p < HPL; p++) acc[h][p] = 0.f;

    for (int i = o0; i < o1; i++) {
        int s = __ldg(&csrc[i]);
        float a = 0.f;
        if (lane < H) {
            float v = __ldg(&es[s * H + lane]) + edv;
            v = v > 0.f ? v : 0.2f * v;
            a = __expf(v);
            smv += a;
        }
        float ah[H];
#pragma unroll
        for (int h = 0; h < H; h++) ah[h] = __shfl_sync(0xffffffffu, a, h);
        const __half* row = xin + (size_t)s * KH + lane * HPL;
        float xv[HPL];
        if (HPL == 2) {
            __half2 hv = *(const __half2*)row;
            xv[0] = __low2float(hv); xv[1] = __high2float(hv);
        } else {
            uint4 u = *(const uint4*)row;
            __half2 h0 = *(__half2*)&u.x, h1 = *(__half2*)&u.y;
            __half2 h2 = *(__half2*)&u.z, h3 = *(__half2*)&u.w;
            xv[0] = __low2float(h0); xv[1] = __high2float(h0);
            xv[2] = __low2float(h1); xv[3] = __high2float(h1);
            xv[4] = __low2float(h2); xv[5] = __high2float(h2);
            xv[6] = __low2float(h3); xv[7] = __high2float(h3);
        }
#pragma unroll
        for (int h = 0; h < H; h++)
#pragma unroll
            for (int p = 0; p < HPL; p++) acc[h][p] += ah[h] * xv[p];
    }
    float inv[H];
#pragma unroll
    for (int h = 0; h < H; h++)
        inv[h] = 1.f / __shfl_sync(0xffffffffu, smv, h);
    __half* orow = agg + (size_t)gw * (H * KH);
#pragma unroll
    for (int h = 0; h < H; h++)
#pragma unroll
        for (int p = 0; p < HPL; p += 2)
            *(__half2*)(orow + h * KH + lane * HPL + p) =
                __floats2half2_rn(acc[h][p] * inv[h], acc[h][p + 1] * inv[h]);
}

// ---------------- single-pass layer-2 aggregation of projected h -------------
// row = 256 halfs feature-major (head = j/64); fused bias+ELU; dual out
__global__ __launch_bounds__(256) void gat_agg_ph(const int* __restrict__ off,
                                                  const int* __restrict__ csrc,
                                                  const float* __restrict__ es,
                                                  const float* __restrict__ ed,
                                                  const __half* __restrict__ proj,
                                                  const float* __restrict__ bias,
                                                  float* __restrict__ outf,
                                                  __half* __restrict__ outh) {
    constexpr int H = H12;
    int gw = (blockIdx.x * blockDim.x + threadIdx.x) >> 5;
    int lane = threadIdx.x & 31;
    if (gw >= NNODE) return;
    int o0 = off[gw], o1 = off[gw + 1];
    float edv = (lane < H) ? __ldg(&ed[gw * H + lane]) : 0.f;
    float smv = 0.f;
    float acc[8];
#pragma unroll
    for (int p = 0; p < 8; p++) acc[p] = 0.f;
    int myhead = lane >> 3;   // 8 halfs per lane, 64 per head

    for (int i = o0; i < o1; i++) {
        int s = __ldg(&csrc[i]);
        float a = 0.f;
        if (lane < H) {
            float v = __ldg(&es[s * H + lane]) + edv;
            v = v > 0.f ? v : 0.2f * v;
            a = __expf(v);
            smv += a;
        }
        float av = __shfl_sync(0xffffffffu, a, myhead);
        uint4 u = *(const uint4*)(proj + (size_t)s * D1 + lane * 8);
        __half2 h0 = *(__half2*)&u.x, h1 = *(__half2*)&u.y;
        __half2 h2 = *(__half2*)&u.z, h3 = *(__half2*)&u.w;
        acc[0] += av * __low2float(h0); acc[1] += av * __high2float(h0);
        acc[2] += av * __low2float(h1); acc[3] += av * __high2float(h1);
        acc[4] += av * __low2float(h2); acc[5] += av * __high2float(h2);
        acc[6] += av * __low2float(h3); acc[7] += av * __high2float(h3);
    }
    float inv = 1.f / __shfl_sync(0xffffffffu, smv, myhead);
    float* frow = outf + (size_t)gw * D1 + lane * 8;
    __half* hrow = outh + (size_t)gw * D1 + lane * 8;
#pragma unroll
    for (int p = 0; p < 8; p += 2) {
        float v0 = acc[p] * inv + bias[lane * 8 + p];
        float v1 = acc[p + 1] * inv + bias[lane * 8 + p + 1];
        v0 = v0 > 0.f ? v0 : expm1f(v0);
        v1 = v1 > 0.f ? v1 : expm1f(v1);
        *(float2*)(frow + p) = make_float2(v0, v1);
        *(__half2*)(hrow + p) = __floats2half2_rn(v0, v1);
    }
}

// ---------------- pooling + head --------------------------------------------
__global__ void pool_feat_v4(const float4* __restrict__ aggr, const int* __restrict__ batch,
                             float4* __restrict__ pool) {
    const int RV = D3P / 4;
    int i = blockIdx.x * blockDim.x + threadIdx.x;
    if (i >= NNODE * RV) return;
    int n = i / RV, j = i - n * RV;
    red_v4(&pool[batch[n] * RV + j], aggr[i]);
}
__global__ void pool_cnt(const int* __restrict__ batch, float* __restrict__ cnt) {
    int n = blockIdx.x * blockDim.x + threadIdx.x;
    if (n < NNODE) atomicAdd(&cnt[batch[n]], 1.f);
}
__global__ void head_kernel(const float* __restrict__ pool, const float* __restrict__ cnt,
                            const float* __restrict__ wp, const float* __restrict__ bp,
                            float* __restrict__ out) {
    __shared__ float gm[OUT3];
    int b = blockIdx.x;
    float inv = 1.f / fmaxf(cnt[b], 1.f);
    for (int o = threadIdx.x; o < OUT3; o += blockDim.x) {
        float s = 0.f;
#pragma unroll
        for (int h = 0; h < H3; h++) s += pool[b * D3P + h * 128 + o];
        gm[o] = s * inv * (1.f / H3);
    }
    __syncthreads();
    if (threadIdx.x < NCLS) {
        float acc = bp[threadIdx.x];
        for (int o = 0; o < OUT3; o++) acc += gm[o] * wp[o * NCLS + threadIdx.x];
        out[b * NCLS + threadIdx.x] = acc;
    }
}

// ---------------- host orchestration ----------------------------------------
extern "C" void kernel_launch(void* const* d_in, const int* in_sizes, int n_in,
                              void* d_out, int out_size) {
    const int*   x    = (const int*)d_in[0];
    const int*   nd   = (const int*)d_in[1];
    const int*   ei   = (const int*)d_in[2];
    const int*   bat  = (const int*)d_in[3];
    const float* nemb = (const float*)d_in[4];
    const float* demb = (const float*)d_in[5];
    const float* w1   = (const float*)d_in[6];
    const float* as1  = (const float*)d_in[7];
    const float* ad1  = (const float*)d_in[8];
    const float* b1   = (const float*)d_in[9];
    const float* w2   = (const float*)d_in[10];
    const float* as2  = (const float*)d_in[11];
    const float* ad2  = (const float*)d_in[12];
    const float* b2   = (const float*)d_in[13];
    const float* w3   = (const float*)d_in[14];
    const float* as3  = (const float*)d_in[15];
    const float* ad3  = (const float*)d_in[16];
    const float* b3   = (const float*)d_in[17];
    const float* wp   = (const float*)d_in[18];
    const float* bp   = (const float*)d_in[19];
    float* out = (float*)d_out;

    float *x0, *feat, *feat2, *aggr, *es, *ed;
    float *va1, *vd1, *va2, *vd2, *va3, *vd3, *b3p, *pool, *cnt;
    __half *x0h, *p1h, *feath, *projh, *feat2h, *agg3h, *w1t, *w2t, *w3t;
    int *deg, *off, *cur, *csrc, *bsum, *bpre;
    cudaGetSymbolAddress((void**)&x0,    g_x0);
    cudaGetSymbolAddress((void**)&x0h,   g_x0h);
    cudaGetSymbolAddress((void**)&p1h,   g_p1h);
    cudaGetSymbolAddress((void**)&feat,  g_feat);
    cudaGetSymbolAddress((void**)&feath, g_feath);
    cudaGetSymbolAddress((void**)&projh, g_projh);
    cudaGetSymbolAddress((void**)&feat2, g_feat2);
    cudaGetSymbolAddress((void**)&feat2h,g_feat2h);
    cudaGetSymbolAddress((void**)&agg3h, g_agg3h);
    cudaGetSymbolAddress((void**)&aggr,  g_aggr);
    cudaGetSymbolAddress((void**)&es,    g_es);
    cudaGetSymbolAddress((void**)&ed,    g_ed);
    cudaGetSymbolAddress((void**)&va1,   g_va1);
    cudaGetSymbolAddress((void**)&vd1,   g_vd1);
    cudaGetSymbolAddress((void**)&va2,   g_va2);
    cudaGetSymbolAddress((void**)&vd2,   g_vd2);
    cudaGetSymbolAddress((void**)&va3,   g_va3);
    cudaGetSymbolAddress((void**)&vd3,   g_vd3);
    cudaGetSymbolAddress((void**)&w1t,   g_w1t);
    cudaGetSymbolAddress((void**)&w2t,   g_w2t);
    cudaGetSymbolAddress((void**)&w3t,   g_w3t);
    cudaGetSymbolAddress((void**)&b3p,   g_b3p);
    cudaGetSymbolAddress((void**)&pool,  g_pool);
    cudaGetSymbolAddress((void**)&cnt,   g_cnt);
    cudaGetSymbolAddress((void**)&deg,   g_deg);
    cudaGetSymbolAddress((void**)&off,   g_off);
    cudaGetSymbolAddress((void**)&cur,   g_cur);
    cudaGetSymbolAddress((void**)&csrc,  g_csrc);
    cudaGetSymbolAddress((void**)&bsum,  g_bsum);
    cudaGetSymbolAddress((void**)&bpre,  g_bpre);

    const int TB = 256;
    const int eb = (ETOT + TB - 1) / TB;
    const int nb = (NNODE * 32 + TB - 1) / TB;   // warp per node
    const int ab = (NNODE + 7) / 8;
    const int SB = (NNODE + 1023) / 1024;
    const int MB = (NNODE + 127) / 128;

    // launches 0-4, then attn_small L1 at index 5 (profiled)
    cudaMemsetAsync(deg, 0, NNODE * 4);
    cudaMemsetAsync(cur, 0, NNODE * 4);
    count_deg<<<eb, TB>>>(ei, deg);
    node_enc<<<(NNODE * EMB + TB - 1) / TB, TB>>>(x, nd, nemb, demb, x0, x0h);
    make_va<<<(EMB * H12 + D1 * H12 + D1 * H3 + TB - 1) / TB, TB>>>(
        w1, as1, ad1, w2, as2, ad2, w3, as3, ad3, va1, vd1, va2, vd2, va3, vd3);
    attn_small<EMB, H12><<<ab, TB>>>(x0, va1, vd1, es, ed);
    prep_weights<<<(16384 + 65536 + H3 * 128 * D1 + TB - 1) / TB, TB>>>(
        w1, w2, w3, b3, w1t, w2t, w3t, b3p);
    deg_part<<<SB, 1024>>>(deg, bsum);
    scan_bsum<<<1, 32>>>(bsum, bpre, off, SB);
    deg_scan<<<SB, 1024>>>(deg, bpre, off);
    scatter_edges<<<eb, TB>>>(ei, off, cur, csrc);

    // ---- layer 1: aggregate x0h (K=64/head), per-head fp16 GEMM ----
    gat_agg_xh<H12, 2><<<nb, TB>>>(off, csrc, es, ed, x0h, p1h);
    {
        dim3 g(1, MB, H12);   // [N,64] @ [64,64] per head -> feat[:, h*64..]
        gemm_h16<64><<<g, 256>>>(p1h, w1t, feat, feath, b1, NNODE, EMB,
                                 D1, EMB, D1, EMB, 64 * EMB, EMB, EMB, 1);
    }

    // ---- layer 2: projh = feath@w2 (fp16), single-pass aggregate ----
    {
        dim3 g(2, MB, 1);
        gemm_h16<128><<<g, 256>>>(feath, w2t, nullptr, projh, nullptr, NNODE, D1,
                                  D1, D1, D1, 0, 0, 0, 0, 0);
    }
    attn_small<D1, H12><<<ab, TB>>>(feat, va2, vd2, es, ed);
    gat_agg_ph<<<nb, TB>>>(off, csrc, es, ed, projh, b2, feat2, feat2h);

    // ---- layer 3: aggregate feat2h per 6 heads, per-head fp16 GEMM ----
    attn_small<D1, H3><<<ab, TB>>>(feat2, va3, vd3, es, ed);
    gat_agg_xh<H3, 8><<<nb, TB>>>(off, csrc, es, ed, feat2h, agg3h);
    {
        dim3 g(1, MB, H3);    // [N,256] @ [256,128] per head -> aggr[:, h*128..]
        gemm_h16<128><<<g, 256>>>(agg3h, w3t, aggr, nullptr, b3p, NNODE, D1,
                                  H3 * D1, D1, D3P, D1, 128 * D1, 128, 128, 0);
    }

    // ---- pooling + classifier head ----
    cudaMemsetAsync(pool, 0, NB * D3P * 4);
    cudaMemsetAsync(cnt, 0, NB * 4);
    pool_feat_v4<<<(NNODE * (D3P / 4) + TB - 1) / TB, TB>>>((const float4*)aggr, bat, (float4*)pool);
    pool_cnt<<<(NNODE + TB - 1) / TB, TB>>>(bat, cnt);
    head_kernel<<<NB, 128>>>(pool, cnt, wp, bp, out);
}

// round 10
// speedup vs baseline: 3.6323x; 1.1053x over previous
#include <cuda_runtime.h>
#include <cuda_fp16.h>
#include <math.h>

#define NNODE 30000
#define NEDGE 300000
#define ETOT  330000
#define NB    300
#define EMB   64
#define D1    256
#define H12   4
#define H3    6
#define OUT3  121
#define D3    726
#define D3P   768
#define NCLS  10

// ---------------- scratch ----------------------------------------------------
__device__ float  g_x0   [NNODE * EMB];
__device__ __half g_x0h  [NNODE * EMB];
__device__ __half g_p1h  [NNODE * D1];
__device__ float  g_feat [NNODE * D1];
__device__ __half g_feath[NNODE * D1];
__device__ __half g_projh[NNODE * D1];
__device__ float  g_feat2[NNODE * D1];
__device__ __half g_feat2h[NNODE * D1];
__device__ __half g_agg3h[NNODE * (H3 * D1)];
__device__ float  g_es  [NNODE * H3];
__device__ float  g_ed  [NNODE * H3];
// va/vd transposed: [h][K]
__device__ float  g_va1[H12 * EMB], g_vd1[H12 * EMB];
__device__ float  g_va2[H12 * D1],  g_vd2[H12 * D1];
__device__ float  g_va3[H3 * D1],   g_vd3[H3 * D1];
__device__ __half g_w1t[H12 * 64 * 64];
__device__ __half g_w2t[D1 * D1];
__device__ __half g_w3t[H3 * 128 * D1];
__device__ float  g_b3p[D3P];
__device__ float  g_pool[NB * D3P];
__device__ float  g_cnt [NB];
__device__ int    g_deg [NNODE];
__device__ int    g_off [NNODE + 1];
__device__ int    g_cur [NNODE];
__device__ int    g_csrc[ETOT];
__device__ int    g_bsum[32];
__device__ int    g_bpre[32];

__device__ __forceinline__ void red_v2(float* addr, float v0, float v1) {
    asm volatile("red.global.add.v2.f32 [%0], {%1,%2};" ::
                 "l"(addr), "f"(v0), "f"(v1) : "memory");
}

// ---------------- node encoder ----------------------------------------------
__global__ void node_enc(const int* __restrict__ x, const int* __restrict__ nd,
                         const float* __restrict__ ne, const float* __restrict__ de,
                         float* __restrict__ out, __half* __restrict__ outh) {
    int i = blockIdx.x * blockDim.x + threadIdx.x;
    if (i >= NNODE * EMB) return;
    int n = i >> 6, d = i & 63;
    float v = ne[x[n] * EMB + d] + de[nd[n] * EMB + d];
    out[i] = v;
    outh[i] = __float2half(v);
}

// ---------------- weight prep ------------------------------------------------
__global__ void prep_weights(const float* __restrict__ w1, const float* __restrict__ w2,
                             const float* __restrict__ w3, const float* __restrict__ b3,
                             __half* __restrict__ w1t, __half* __restrict__ w2t,
                             __half* __restrict__ w3t, float* __restrict__ b3p) {
    int i = blockIdx.x * blockDim.x + threadIdx.x;
    if (i < 16384) {
        int h = i >> 12, r = i & 4095, n = r >> 6, k = r & 63;
        w1t[i] = __float2half(w1[k * D1 + h * 64 + n]);
    }
    int j = i - 16384;
    if (j >= 0 && j < 65536) {
        int n = j >> 8, k = j & 255;
        w2t[j] = __float2half(w2[k * D1 + n]);
    }
    int q = i - (16384 + 65536);
    if (q >= 0 && q < H3 * 128 * D1) {
        int h = q >> 15, r = q & 32767, n = r >> 8, k = r & 255;
        w3t[q] = __float2half(n < OUT3 ? w3[k * D3 + h * OUT3 + n] : 0.f);
    }
    if (i < D3P) {
        int h = i >> 7, o = i & 127;
        b3p[i] = (o < OUT3) ? b3[h * OUT3 + o] : 0.f;
    }
}

// va[h*K+k] = sum_d W[k, h*D+d] * a[h*D+d]   (transposed [h][K] layout)
__global__ void make_va(const float* __restrict__ w1, const float* __restrict__ as1, const float* __restrict__ ad1,
                        const float* __restrict__ w2, const float* __restrict__ as2, const float* __restrict__ ad2,
                        const float* __restrict__ w3, const float* __restrict__ as3, const float* __restrict__ ad3,
                        float* __restrict__ va1, float* __restrict__ vd1,
                        float* __restrict__ va2, float* __restrict__ vd2,
                        float* __restrict__ va3, float* __restrict__ vd3) {
    int gid = blockIdx.x * blockDim.x + threadIdx.x;
    if (gid < H12 * EMB) {
        int h = gid >> 6, k = gid & 63;
        float s1 = 0.f, s2 = 0.f;
        for (int d = 0; d < EMB; d++) {
            float w = w1[k * D1 + h * EMB + d];
            s1 += w * as1[h * EMB + d];
            s2 += w * ad1[h * EMB + d];
        }
        va1[gid] = s1; vd1[gid] = s2;
        return;
    }
    gid -= H12 * EMB;
    if (gid < H12 * D1) {
        int h = gid >> 8, k = gid & 255;
        float s1 = 0.f, s2 = 0.f;
        for (int d = 0; d < EMB; d++) {
            float w = w2[k * D1 + h * EMB + d];
            s1 += w * as2[h * EMB + d];
            s2 += w * ad2[h * EMB + d];
        }
        va2[gid] = s1; vd2[gid] = s2;
        return;
    }
    gid -= H12 * D1;
    if (gid < H3 * D1) {
        int h = gid >> 8, k = gid & 255;
        float s1 = 0.f, s2 = 0.f;
        for (int o = 0; o < OUT3; o++) {
            float w = w3[k * D3 + h * OUT3 + o];
            s1 += w * as3[h * OUT3 + o];
            s2 += w * ad3[h * OUT3 + o];
        }
        va3[gid] = s1; vd3[gid] = s2;
    }
}

// ---------------- CSR build --------------------------------------------------
__global__ void count_deg(const int* __restrict__ ei, int* __restrict__ deg) {
    int e = blockIdx.x * blockDim.x + threadIdx.x;
    if (e >= ETOT) return;
    int d = (e < NEDGE) ? ei[NEDGE + e] : e - NEDGE;
    atomicAdd(&deg[d], 1);
}
__global__ __launch_bounds__(1024) void deg_part(const int* __restrict__ deg,
                                                 int* __restrict__ bsum) {
    __shared__ int ws[32];
    int t = threadIdx.x, lane = t & 31, w = t >> 5;
    int idx = blockIdx.x * 1024 + t;
    int v = (idx < NNODE) ? deg[idx] : 0;
#pragma unroll
    for (int o = 16; o; o >>= 1) v += __shfl_xor_sync(0xffffffffu, v, o);
    if (lane == 0) ws[w] = v;
    __syncthreads();
    if (t < 32) {
        int s = ws[t];
#pragma unroll
        for (int o = 16; o; o >>= 1) s += __shfl_xor_sync(0xffffffffu, s, o);
        if (t == 0) bsum[blockIdx.x] = s;
    }
}
__global__ void scan_bsum(const int* __restrict__ bsum, int* __restrict__ bpre,
                          int* __restrict__ off, int nblk) {
    int t = threadIdx.x;
    int v = (t < nblk) ? bsum[t] : 0;
    int own = v;
#pragma unroll
    for (int o = 1; o < 32; o <<= 1) {
        int y = __shfl_up_sync(0xffffffffu, v, o);
        if (t >= o) v += y;
    }
    if (t < nblk) bpre[t] = v - own;
    if (t == 31) off[NNODE] = v;
}
__global__ __launch_bounds__(1024) void deg_scan(const int* __restrict__ deg,
                                                 const int* __restrict__ bpre,
                                                 int* __restrict__ off) {
    __shared__ int ws[32];
    int t = threadIdx.x, lane = t & 31, w = t >> 5;
    int idx = blockIdx.x * 1024 + t;
    int v = (idx < NNODE) ? deg[idx] : 0;
    int x = v;
#pragma unroll
    for (int o = 1; o < 32; o <<= 1) {
        int y = __shfl_up_sync(0xffffffffu, x, o);
        if (lane >= o) x += y;
    }
    if (lane == 31) ws[w] = x;
    __syncthreads();
    if (w == 0) {
        int y = ws[lane];
#pragma unroll
        for (int o = 1; o < 32; o <<= 1) {
            int z = __shfl_up_sync(0xffffffffu, y, o);
            if (lane >= o) y += z;
        }
        ws[lane] = y;
    }
    __syncthreads();
    int excl = x - v + (w ? ws[w - 1] : 0) + bpre[blockIdx.x];
    if (idx < NNODE) off[idx] = excl;
}
__global__ void scatter_edges(const int* __restrict__ ei, const int* __restrict__ off,
                              int* __restrict__ cur, int* __restrict__ csrc) {
    int e = blockIdx.x * blockDim.x + threadIdx.x;
    if (e >= ETOT) return;
    int s, d;
    if (e < NEDGE) { s = ei[e]; d = ei[NEDGE + e]; }
    else           { s = d = e - NEDGE; }
    int slot = off[d] + atomicAdd(&cur[d], 1);
    csrc[slot] = s;
}

// ---------------- fp16 tensor GEMM: C[M,N] = A[M,K] @ Bt[N,K]^T --------------
template <int BN>
__global__ __launch_bounds__(256) void gemm_h16(
        const __half* __restrict__ A, const __half* __restrict__ Bt,
        float* __restrict__ C, __half* __restrict__ Ch, const float* __restrict__ bias,
        int M, int K, int lda, int ldb, int ldc,
        int aHS, int bHS, int cHS, int biasHS, int elu) {
    constexpr int AST = 40;
    constexpr int WN = BN / 2;
    constexpr int JT = WN / 8;
    __shared__ __half As[128 * AST];
    __shared__ __half Bs[BN * AST];
    int t = threadIdx.x;
    int warp = t >> 5, lane = t & 31;
    int tg = lane >> 2, t4 = lane & 3;
    int bm = blockIdx.y * 128, bn = blockIdx.x * BN;
    int z = blockIdx.z;
    const __half* Az = A + (size_t)aHS * z;
    const __half* Bz = Bt + (size_t)bHS * z;
    int wm = (warp & 3) * 32, wn = (warp >> 2) * WN;
    float c[2][JT][4];
#pragma unroll
    for (int i = 0; i < 2; i++)
#pragma unroll
        for (int j = 0; j < JT; j++)
#pragma unroll
            for (int q = 0; q < 4; q++) c[i][j][q] = 0.f;

    for (int k0 = 0; k0 < K; k0 += 32) {
#pragma unroll
        for (int i = 0; i < 2; i++) {
            int v = t + 256 * i;
            int row = v >> 2, kc = (v & 3) * 8;
            uint4 u = make_uint4(0u, 0u, 0u, 0u);
            int gr = bm + row;
            if (gr < M) u = *(const uint4*)(Az + (size_t)gr * lda + k0 + kc);
            *(uint4*)&As[row * AST + kc] = u;
        }
#pragma unroll
        for (int i = 0; i < BN / 64; i++) {
            int v = t + 256 * i;
            int row = v >> 2, kc = (v & 3) * 8;
            *(uint4*)&Bs[row * AST + kc] =
                *(const uint4*)(Bz + (size_t)(bn + row) * ldb + k0 + kc);
        }
        __syncthreads();
#pragma unroll
        for (int ks = 0; ks < 2; ks++) {
            int kb = ks * 16;
            unsigned a[2][4], b[JT][2];
#pragma unroll
            for (int i = 0; i < 2; i++) {
                int r = wm + 16 * i + tg;
                a[i][0] = *(const unsigned*)&As[r * AST + kb + 2 * t4];
                a[i][1] = *(const unsigned*)&As[(r + 8) * AST + kb + 2 * t4];
                a[i][2] = *(const unsigned*)&As[r * AST + kb + 2 * t4 + 8];
                a[i][3] = *(const unsigned*)&As[(r + 8) * AST + kb + 2 * t4 + 8];
            }
#pragma unroll
            for (int j = 0; j < JT; j++) {
                int n = wn + 8 * j + tg;
                b[j][0] = *(const unsigned*)&Bs[n * AST + kb + 2 * t4];
                b[j][1] = *(const unsigned*)&Bs[n * AST + kb + 2 * t4 + 8];
            }
#pragma unroll
            for (int i = 0; i < 2; i++)
#pragma unroll
                for (int j = 0; j < JT; j++) {
                    asm volatile(
                        "mma.sync.aligned.m16n8k16.row.col.f32.f16.f16.f32 "
                        "{%0,%1,%2,%3}, {%4,%5,%6,%7}, {%8,%9}, {%0,%1,%2,%3};"
                        : "+f"(c[i][j][0]), "+f"(c[i][j][1]),
                          "+f"(c[i][j][2]), "+f"(c[i][j][3])
                        : "r"(a[i][0]), "r"(a[i][1]), "r"(a[i][2]), "r"(a[i][3]),
                          "r"(b[j][0]), "r"(b[j][1]));
                }
        }
        __syncthreads();
    }
#pragma unroll
    for (int i = 0; i < 2; i++)
#pragma unroll
        for (int j = 0; j < JT; j++) {
            int r = bm + wm + 16 * i + tg;
            int cc = bn + wn + 8 * j + 2 * t4;
            float v0 = c[i][j][0], v1 = c[i][j][1];
            float v2 = c[i][j][2], v3 = c[i][j][3];
            if (bias) {
                float b0 = bias[biasHS * z + cc], b1 = bias[biasHS * z + cc + 1];
                v0 += b0; v1 += b1; v2 += b0; v3 += b1;
            }
            if (elu) {
                v0 = v0 > 0.f ? v0 : expm1f(v0);
                v1 = v1 > 0.f ? v1 : expm1f(v1);
                v2 = v2 > 0.f ? v2 : expm1f(v2);
                v3 = v3 > 0.f ? v3 : expm1f(v3);
            }
            if (C) {
                float* Cz = C + (size_t)cHS * z;
                if (r < M)     *(float2*)(Cz + (size_t)r * ldc + cc)       = make_float2(v0, v1);
                if (r + 8 < M) *(float2*)(Cz + (size_t)(r + 8) * ldc + cc) = make_float2(v2, v3);
            }
            if (Ch) {
                __half* Hz = Ch + (size_t)cHS * z;
                if (r < M)     *(__half2*)(Hz + (size_t)r * ldc + cc)       = __floats2half2_rn(v0, v1);
                if (r + 8 < M) *(__half2*)(Hz + (size_t)(r + 8) * ldc + cc) = __floats2half2_rn(v2, v3);
            }
        }
}

// ---------------- layer-3 GEMM with fused mean-pool epilogue -----------------
// grid (1, MB, H3); output col block = z*128 within D3P; atomically pools rows.
__global__ __launch_bounds__(256) void gemm_h16_pool(
        const __half* __restrict__ A, const __half* __restrict__ Bt,
        const int* __restrict__ bat, float* __restrict__ pool,
        int M, int K, int lda, int ldb, int aHS, int bHS) {
    constexpr int BN = 128, AST = 40, WN = 64, JT = 8;
    __shared__ __half As[128 * AST];
    __shared__ __half Bs[BN * AST];
    int t = threadIdx.x;
    int warp = t >> 5, lane = t & 31;
    int tg = lane >> 2, t4 = lane & 3;
    int bm = blockIdx.y * 128;
    int z = blockIdx.z;
    const __half* Az = A + (size_t)aHS * z;
    const __half* Bz = Bt + (size_t)bHS * z;
    int wm = (warp & 3) * 32, wn = (warp >> 2) * WN;
    float c[2][JT][4];
#pragma unroll
    for (int i = 0; i < 2; i++)
#pragma unroll
        for (int j = 0; j < JT; j++)
#pragma unroll
            for (int q = 0; q < 4; q++) c[i][j][q] = 0.f;

    for (int k0 = 0; k0 < K; k0 += 32) {
#pragma unroll
        for (int i = 0; i < 2; i++) {
            int v = t + 256 * i;
            int row = v >> 2, kc = (v & 3) * 8;
            uint4 u = make_uint4(0u, 0u, 0u, 0u);
            int gr = bm + row;
            if (gr < M) u = *(const uint4*)(Az + (size_t)gr * lda + k0 + kc);
            *(uint4*)&As[row * AST + kc] = u;
        }
#pragma unroll
        for (int i = 0; i < 2; i++) {
            int v = t + 256 * i;
            int row = v >> 2, kc = (v & 3) * 8;
            *(uint4*)&Bs[row * AST + kc] =
                *(const uint4*)(Bz + (size_t)row * ldb + k0 + kc);
        }
        __syncthreads();
#pragma unroll
        for (int ks = 0; ks < 2; ks++) {
            int kb = ks * 16;
            unsigned a[2][4], b[JT][2];
#pragma unroll
            for (int i = 0; i < 2; i++) {
                int r = wm + 16 * i + tg;
                a[i][0] = *(const unsigned*)&As[r * AST + kb + 2 * t4];
                a[i][1] = *(const unsigned*)&As[(r + 8) * AST + kb + 2 * t4];
                a[i][2] = *(const unsigned*)&As[r * AST + kb + 2 * t4 + 8];
                a[i][3] = *(const unsigned*)&As[(r + 8) * AST + kb + 2 * t4 + 8];
            }
#pragma unroll
            for (int j = 0; j < JT; j++) {
                int n = wn + 8 * j + tg;
                b[j][0] = *(const unsigned*)&Bs[n * AST + kb + 2 * t4];
                b[j][1] = *(const unsigned*)&Bs[n * AST + kb + 2 * t4 + 8];
            }
#pragma unroll
            for (int i = 0; i < 2; i++)
#pragma unroll
                for (int j = 0; j < JT; j++) {
                    asm volatile(
                        "mma.sync.aligned.m16n8k16.row.col.f32.f16.f16.f32 "
                        "{%0,%1,%2,%3}, {%4,%5,%6,%7}, {%8,%9}, {%0,%1,%2,%3};"
                        : "+f"(c[i][j][0]), "+f"(c[i][j][1]),
                          "+f"(c[i][j][2]), "+f"(c[i][j][3])
                        : "r"(a[i][0]), "r"(a[i][1]), "r"(a[i][2]), "r"(a[i][3]),
                          "r"(b[j][0]), "r"(b[j][1]));
                }
        }
        __syncthreads();
    }
#pragma unroll
    for (int i = 0; i < 2; i++)
#pragma unroll
        for (int j = 0; j < JT; j++) {
            int r = bm + wm + 16 * i + tg;
            int cc = z * 128 + wn + 8 * j + 2 * t4;
            if (r < M) {
                int b = __ldg(&bat[r]);
                red_v2(&pool[(size_t)b * D3P + cc], c[i][j][0], c[i][j][1]);
            }
            if (r + 8 < M) {
                int b = __ldg(&bat[r + 8]);
                red_v2(&pool[(size_t)b * D3P + cc], c[i][j][2], c[i][j][3]);
            }
        }
}

// ---------------- es/ed: [N,K] @ va/vd ([h][K] layout, float4, no conflicts) -
template <int K, int H>
__global__ __launch_bounds__(256) void attn_small(const float* __restrict__ feat,
                                                  const float* __restrict__ va,
                                                  const float* __restrict__ vd,
                                                  float* __restrict__ es,
                                                  float* __restrict__ ed) {
    constexpr int K4 = K / 4;
    __shared__ float4 sva[H * K4], svd[H * K4];
    int t = threadIdx.x;
    for (int i = t; i < H * K4; i += 256) {
        sva[i] = ((const float4*)va)[i];
        svd[i] = ((const float4*)vd)[i];
    }
    __syncthreads();
    int gw = blockIdx.x * 8 + (t >> 5);
    int lane = t & 31;
    if (gw >= NNODE) return;
    const float4* row = (const float4*)(feat + (size_t)gw * K);
    float e1[H], e2[H];
#pragma unroll
    for (int h = 0; h < H; h++) { e1[h] = 0.f; e2[h] = 0.f; }
#pragma unroll
    for (int k4 = lane; k4 < K4; k4 += 32) {
        float4 xv = __ldg(&row[k4]);
#pragma unroll
        for (int h = 0; h < H; h++) {
            float4 a = sva[h * K4 + k4];
            float4 b = svd[h * K4 + k4];
            e1[h] += xv.x * a.x + xv.y * a.y + xv.z * a.z + xv.w * a.w;
            e2[h] += xv.x * b.x + xv.y * b.y + xv.z * b.z + xv.w * b.w;
        }
    }
#pragma unroll
    for (int h = 0; h < H; h++)
#pragma unroll
        for (int o = 16; o; o >>= 1) {
            e1[h] += __shfl_xor_sync(0xffffffffu, e1[h], o);
            e2[h] += __shfl_xor_sync(0xffffffffu, e2[h], o);
        }
    if (lane == 0)
#pragma unroll
        for (int h = 0; h < H; h++) {
            es[gw * H + h] = e1[h];
            ed[gw * H + h] = e2[h];
        }
}

// ---------------- single-pass per-head x aggregation (layers 1 & 3) ---------
template <int H, int HPL>
__global__ __launch_bounds__(256) void gat_agg_xh(const int* __restrict__ off,
                                                  const int* __restrict__ csrc,
                                                  const float* __restrict__ es,
                                                  const float* __restrict__ ed,
                                                  const __half* __restrict__ xin,
                                                  __half* __restrict__ agg) {
    constexpr int KH = 32 * HPL;
    int gw = (blockIdx.x * blockDim.x + threadIdx.x) >> 5;
    int lane = threadIdx.x & 31;
    if (gw >= NNODE) return;
    int o0 = off[gw], o1 = off[gw + 1];
    float edv = (lane < H) ? __ldg(&ed[gw * H + lane]) : 0.f;
    float smv = 0.f;
    float acc[H][HPL];
#pragma unroll
    for (int h = 0; h < H; h++)
#pragma unroll
        for (int p = 0; p < HPL; p++) acc[h][p] = 0.f;

    for (int i = o0; i < o1; i++) {
        int s = __ldg(&csrc[i]);
        float a = 0.f;
        if (lane < H) {
            float v = __ldg(&es[s * H + lane]) + edv;
            v = v > 0.f ? v : 0.2f * v;
            a = __expf(v);
            smv += a;
        }
        float ah[H];
#pragma unroll
        for (int h = 0; h < H; h++) ah[h] = __shfl_sync(0xffffffffu, a, h);
        const __half* row = xin + (size_t)s * KH + lane * HPL;
        float xv[HPL];
        if (HPL == 2) {
            __half2 hv = *(const __half2*)row;
            xv[0] = __low2float(hv); xv[1] = __high2float(hv);
        } else {
            uint4 u = *(const uint4*)row;
            __half2 h0 = *(__half2*)&u.x, h1 = *(__half2*)&u.y;
            __half2 h2 = *(__half2*)&u.z, h3 = *(__half2*)&u.w;
            xv[0] = __low2float(h0); xv[1] = __high2float(h0);
            xv[2] = __low2float(h1); xv[3] = __high2float(h1);
            xv[4] = __low2float(h2); xv[5] = __high2float(h2);
            xv[6] = __low2float(h3); xv[7] = __high2float(h3);
        }
#pragma unroll
        for (int h = 0; h < H; h++)
#pragma unroll
            for (int p = 0; p < HPL; p++) acc[h][p] += ah[h] * xv[p];
    }
    float inv[H];
#pragma unroll
    for (int h = 0; h < H; h++)
        inv[h] = 1.f / __shfl_sync(0xffffffffu, smv, h);
    __half* orow = agg + (size_t)gw * (H * KH);
#pragma unroll
    for (int h = 0; h < H; h++)
#pragma unroll
        for (int p = 0; p < HPL; p += 2)
            *(__half2*)(orow + h * KH + lane * HPL + p) =
                __floats2half2_rn(acc[h][p] * inv[h], acc[h][p + 1] * inv[h]);
}

// ---------------- single-pass layer-2 aggregation ----------------------------
__global__ __launch_bounds__(256) void gat_agg_ph(const int* __restrict__ off,
                                                  const int* __restrict__ csrc,
                                                  const float* __restrict__ es,
                                                  const float* __restrict__ ed,
                                                  const __half* __restrict__ proj,
                                                  const float* __restrict__ bias,
                                                  float* __restrict__ outf,
                                                  __half* __restrict__ outh) {
    constexpr int H = H12;
    int gw = (blockIdx.x * blockDim.x + threadIdx.x) >> 5;
    int lane = threadIdx.x & 31;
    if (gw >= NNODE) return;
    int o0 = off[gw], o1 = off[gw + 1];
    float edv = (lane < H) ? __ldg(&ed[gw * H + lane]) : 0.f;
    float smv = 0.f;
    float acc[8];
#pragma unroll
    for (int p = 0; p < 8; p++) acc[p] = 0.f;
    int myhead = lane >> 3;

    for (int i = o0; i < o1; i++) {
        int s = __ldg(&csrc[i]);
        float a = 0.f;
        if (lane < H) {
            float v = __ldg(&es[s * H + lane]) + edv;
            v = v > 0.f ? v : 0.2f * v;
            a = __expf(v);
            smv += a;
        }
        float av = __shfl_sync(0xffffffffu, a, myhead);
        uint4 u = *(const uint4*)(proj + (size_t)s * D1 + lane * 8);
        __half2 h0 = *(__half2*)&u.x, h1 = *(__half2*)&u.y;
        __half2 h2 = *(__half2*)&u.z, h3 = *(__half2*)&u.w;
        acc[0] += av * __low2float(h0); acc[1] += av * __high2float(h0);
        acc[2] += av * __low2float(h1); acc[3] += av * __high2float(h1);
        acc[4] += av * __low2float(h2); acc[5] += av * __high2float(h2);
        acc[6] += av * __low2float(h3); acc[7] += av * __high2float(h3);
    }
    float inv = 1.f / __shfl_sync(0xffffffffu, smv, myhead);
    float* frow = outf + (size_t)gw * D1 + lane * 8;
    __half* hrow = outh + (size_t)gw * D1 + lane * 8;
#pragma unroll
    for (int p = 0; p < 8; p += 2) {
        float v0 = acc[p] * inv + bias[lane * 8 + p];
        float v1 = acc[p + 1] * inv + bias[lane * 8 + p + 1];
        v0 = v0 > 0.f ? v0 : expm1f(v0);
        v1 = v1 > 0.f ? v1 : expm1f(v1);
        *(float2*)(frow + p) = make_float2(v0, v1);
        *(__half2*)(hrow + p) = __floats2half2_rn(v0, v1);
    }
}

// ---------------- pooling count + head ---------------------------------------
__global__ void pool_cnt(const int* __restrict__ batch, float* __restrict__ cnt) {
    int n = blockIdx.x * blockDim.x + threadIdx.x;
    if (n < NNODE) atomicAdd(&cnt[batch[n]], 1.f);
}
__global__ void head_kernel(const float* __restrict__ pool, const float* __restrict__ cnt,
                            const float* __restrict__ b3p,
                            const float* __restrict__ wp, const float* __restrict__ bp,
                            float* __restrict__ out) {
    __shared__ float gm[OUT3];
    int b = blockIdx.x;
    float inv = 1.f / fmaxf(cnt[b], 1.f);
    for (int o = threadIdx.x; o < OUT3; o += blockDim.x) {
        float s = 0.f, sb = 0.f;
#pragma unroll
        for (int h = 0; h < H3; h++) {
            s += pool[b * D3P + h * 128 + o];
            sb += b3p[h * 128 + o];
        }
        gm[o] = (s * inv + sb) * (1.f / H3);
    }
    __syncthreads();
    if (threadIdx.x < NCLS) {
        float acc = bp[threadIdx.x];
        for (int o = 0; o < OUT3; o++) acc += gm[o] * wp[o * NCLS + threadIdx.x];
        out[b * NCLS + threadIdx.x] = acc;
    }
}

// ---------------- host orchestration ----------------------------------------
extern "C" void kernel_launch(void* const* d_in, const int* in_sizes, int n_in,
                              void* d_out, int out_size) {
    const int*   x    = (const int*)d_in[0];
    const int*   nd   = (const int*)d_in[1];
    const int*   ei   = (const int*)d_in[2];
    const int*   bat  = (const int*)d_in[3];
    const float* nemb = (const float*)d_in[4];
    const float* demb = (const float*)d_in[5];
    const float* w1   = (const float*)d_in[6];
    const float* as1  = (const float*)d_in[7];
    const float* ad1  = (const float*)d_in[8];
    const float* b1   = (const float*)d_in[9];
    const float* w2   = (const float*)d_in[10];
    const float* as2  = (const float*)d_in[11];
    const float* ad2  = (const float*)d_in[12];
    const float* b2   = (const float*)d_in[13];
    const float* w3   = (const float*)d_in[14];
    const float* as3  = (const float*)d_in[15];
    const float* ad3  = (const float*)d_in[16];
    const float* b3   = (const float*)d_in[17];
    const float* wp   = (const float*)d_in[18];
    const float* bp   = (const float*)d_in[19];
    float* out = (float*)d_out;

    float *x0, *feat, *feat2, *es, *ed;
    float *va1, *vd1, *va2, *vd2, *va3, *vd3, *b3p, *pool, *cnt;
    __half *x0h, *p1h, *feath, *projh, *feat2h, *agg3h, *w1t, *w2t, *w3t;
    int *deg, *off, *cur, *csrc, *bsum, *bpre;
    cudaGetSymbolAddress((void**)&x0,    g_x0);
    cudaGetSymbolAddress((void**)&x0h,   g_x0h);
    cudaGetSymbolAddress((void**)&p1h,   g_p1h);
    cudaGetSymbolAddress((void**)&feat,  g_feat);
    cudaGetSymbolAddress((void**)&feath, g_feath);
    cudaGetSymbolAddress((void**)&projh, g_projh);
    cudaGetSymbolAddress((void**)&feat2, g_feat2);
    cudaGetSymbolAddress((void**)&feat2h,g_feat2h);
    cudaGetSymbolAddress((void**)&agg3h, g_agg3h);
    cudaGetSymbolAddress((void**)&es,    g_es);
    cudaGetSymbolAddress((void**)&ed,    g_ed);
    cudaGetSymbolAddress((void**)&va1,   g_va1);
    cudaGetSymbolAddress((void**)&vd1,   g_vd1);
    cudaGetSymbolAddress((void**)&va2,   g_va2);
    cudaGetSymbolAddress((void**)&vd2,   g_vd2);
    cudaGetSymbolAddress((void**)&va3,   g_va3);
    cudaGetSymbolAddress((void**)&vd3,   g_vd3);
    cudaGetSymbolAddress((void**)&w1t,   g_w1t);
    cudaGetSymbolAddress((void**)&w2t,   g_w2t);
    cudaGetSymbolAddress((void**)&w3t,   g_w3t);
    cudaGetSymbolAddress((void**)&b3p,   g_b3p);
    cudaGetSymbolAddress((void**)&pool,  g_pool);
    cudaGetSymbolAddress((void**)&cnt,   g_cnt);
    cudaGetSymbolAddress((void**)&deg,   g_deg);
    cudaGetSymbolAddress((void**)&off,   g_off);
    cudaGetSymbolAddress((void**)&cur,   g_cur);
    cudaGetSymbolAddress((void**)&csrc,  g_csrc);
    cudaGetSymbolAddress((void**)&bsum,  g_bsum);
    cudaGetSymbolAddress((void**)&bpre,  g_bpre);

    const int TB = 256;
    const int eb = (ETOT + TB - 1) / TB;
    const int nb = (NNODE * 32 + TB - 1) / TB;
    const int ab = (NNODE + 7) / 8;
    const int SB = (NNODE + 1023) / 1024;
    const int MB = (NNODE + 127) / 128;

    cudaMemsetAsync(deg, 0, NNODE * 4);
    cudaMemsetAsync(cur, 0, NNODE * 4);
    cudaMemsetAsync(pool, 0, NB * D3P * 4);
    cudaMemsetAsync(cnt, 0, NB * 4);
    count_deg<<<eb, TB>>>(ei, deg);
    node_enc<<<(NNODE * EMB + TB - 1) / TB, TB>>>(x, nd, nemb, demb, x0, x0h);
    make_va<<<(H12 * EMB + H12 * D1 + H3 * D1 + TB - 1) / TB, TB>>>(
        w1, as1, ad1, w2, as2, ad2, w3, as3, ad3, va1, vd1, va2, vd2, va3, vd3);
    attn_small<EMB, H12><<<ab, TB>>>(x0, va1, vd1, es, ed);
    prep_weights<<<(16384 + 65536 + H3 * 128 * D1 + TB - 1) / TB, TB>>>(
        w1, w2, w3, b3, w1t, w2t, w3t, b3p);
    deg_part<<<SB, 1024>>>(deg, bsum);
    scan_bsum<<<1, 32>>>(bsum, bpre, off, SB);
    deg_scan<<<SB, 1024>>>(deg, bpre, off);
    scatter_edges<<<eb, TB>>>(ei, off, cur, csrc);

    // ---- layer 1 ----
    gat_agg_xh<H12, 2><<<nb, TB>>>(off, csrc, es, ed, x0h, p1h);
    {
        dim3 g(1, MB, H12);
        gemm_h16<64><<<g, 256>>>(p1h, w1t, feat, feath, b1, NNODE, EMB,
                                 D1, EMB, D1, EMB, 64 * EMB, EMB, EMB, 1);
    }

    // ---- layer 2 ----
    {
        dim3 g(2, MB, 1);
        gemm_h16<128><<<g, 256>>>(feath, w2t, nullptr, projh, nullptr, NNODE, D1,
                                  D1, D1, D1, 0, 0, 0, 0, 0);
    }
    attn_small<D1, H12><<<ab, TB>>>(feat, va2, vd2, es, ed);
    gat_agg_ph<<<nb, TB>>>(off, csrc, es, ed, projh, b2, feat2, feat2h);

    // ---- layer 3 (GEMM + fused mean-pool; aHS = D1 per-head offset) ----
    attn_small<D1, H3><<<ab, TB>>>(feat2, va3, vd3, es, ed);
    gat_agg_xh<H3, 8><<<nb, TB>>>(off, csrc, es, ed, feat2h, agg3h);
    pool_cnt<<<(NNODE + TB - 1) / TB, TB>>>(bat, cnt);
    {
        dim3 g(1, MB, H3);
        gemm_h16_pool<<<g, 256>>>(agg3h, w3t, bat, pool, NNODE, D1,
                                  H3 * D1, D1, D1, 128 * D1);
    }

    // ---- classifier head ----
    head_kernel<<<NB, 128>>>(pool, cnt, b3p, wp, bp, out);
}

// round 11
// speedup vs baseline: 4.0362x; 1.1112x over previous
#include <cuda_runtime.h>
#include <cuda_fp16.h>
#include <math.h>

#define NNODE 30000
#define NEDGE 300000
#define ETOT  330000
#define NB    300
#define EMB   64
#define D1    256
#define H12   4
#define H3    6
#define OUT3  121
#define D3    726
#define D3P   768
#define NCLS  10

// ---------------- scratch ----------------------------------------------------
__device__ __half g_x0h  [NNODE * EMB];
__device__ __half g_p1h  [NNODE * D1];
__device__ __half g_feath[NNODE * D1];
__device__ __half g_projh[NNODE * D1];
__device__ __half g_feat2h[NNODE * D1];
__device__ __half g_agg3h[NNODE * (H3 * D1)];
__device__ float  g_es  [NNODE * H3];
__device__ float  g_ed  [NNODE * H3];
// va/vd transposed: [h][K]
__device__ float  g_va1[H12 * EMB], g_vd1[H12 * EMB];
__device__ float  g_va2[H12 * D1],  g_vd2[H12 * D1];
__device__ float  g_va3[H3 * D1],   g_vd3[H3 * D1];
__device__ __half g_w1t[H12 * 64 * 64];
__device__ __half g_w2t[D1 * D1];
__device__ __half g_w3t[H3 * 128 * D1];
__device__ float  g_b3p[D3P];
__device__ float  g_pool[NB * D3P];
__device__ float  g_cnt [NB];
__device__ int    g_deg [NNODE];
__device__ int    g_off [NNODE + 1];
__device__ int    g_cur [NNODE];
__device__ int    g_csrc[ETOT];
__device__ int    g_bsum[32];
__device__ int    g_bpre[32];

__device__ __forceinline__ void red_v2(float* addr, float v0, float v1) {
    asm volatile("red.global.add.v2.f32 [%0], {%1,%2};" ::
                 "l"(addr), "f"(v0), "f"(v1) : "memory");
}

// ---------------- fused setup: node_enc + count_deg + pool_cnt + weights + va
#define SETUP_A (NNODE * EMB)                       // node encoder
#define SETUP_B ETOT                                // count_deg
#define SETUP_C NNODE                               // pool_cnt
#define SETUP_D (16384 + 65536 + H3 * 128 * D1)     // weight prep (>= D3P)
#define SETUP_E (H12 * EMB + H12 * D1 + H3 * D1)    // make_va
#define SETUP_TOTAL (SETUP_A + SETUP_B + SETUP_C + SETUP_D + SETUP_E)

__global__ void setup_all(const int* __restrict__ x, const int* __restrict__ nd,
                          const float* __restrict__ ne, const float* __restrict__ de,
                          const int* __restrict__ ei, const int* __restrict__ bat,
                          const float* __restrict__ w1, const float* __restrict__ as1, const float* __restrict__ ad1,
                          const float* __restrict__ w2, const float* __restrict__ as2, const float* __restrict__ ad2,
                          const float* __restrict__ w3, const float* __restrict__ as3, const float* __restrict__ ad3,
                          const float* __restrict__ b3,
                          __half* __restrict__ x0h, int* __restrict__ deg, float* __restrict__ cnt,
                          __half* __restrict__ w1t, __half* __restrict__ w2t, __half* __restrict__ w3t,
                          float* __restrict__ b3p,
                          float* __restrict__ va1, float* __restrict__ vd1,
                          float* __restrict__ va2, float* __restrict__ vd2,
                          float* __restrict__ va3, float* __restrict__ vd3) {
    int gid = blockIdx.x * blockDim.x + threadIdx.x;
    if (gid < SETUP_A) {            // node encoder -> fp16
        int n = gid >> 6, d = gid & 63;
        x0h[gid] = __float2half(ne[x[n] * EMB + d] + de[nd[n] * EMB + d]);
        return;
    }
    gid -= SETUP_A;
    if (gid < SETUP_B) {            // degree count
        int d = (gid < NEDGE) ? ei[NEDGE + gid] : gid - NEDGE;
        atomicAdd(&deg[d], 1);
        return;
    }
    gid -= SETUP_B;
    if (gid < SETUP_C) {            // per-graph node count
        atomicAdd(&cnt[bat[gid]], 1.f);
        return;
    }
    gid -= SETUP_C;
    if (gid < SETUP_D) {            // weight prep
        int i = gid;
        if (i < 16384) {
            int h = i >> 12, r = i & 4095, n = r >> 6, k = r & 63;
            w1t[i] = __float2half(w1[k * D1 + h * 64 + n]);
        }
        int j = i - 16384;
        if (j >= 0 && j < 65536) {
            int n = j >> 8, k = j & 255;
            w2t[j] = __float2half(w2[k * D1 + n]);
        }
        int q = i - (16384 + 65536);
        if (q >= 0 && q < H3 * 128 * D1) {
            int h = q >> 15, r = q & 32767, n = r >> 8, k = r & 255;
            w3t[q] = __float2half(n < OUT3 ? w3[k * D3 + h * OUT3 + n] : 0.f);
        }
        if (i < D3P) {
            int h = i >> 7, o = i & 127;
            b3p[i] = (o < OUT3) ? b3[h * OUT3 + o] : 0.f;
        }
        return;
    }
    gid -= SETUP_D;
    if (gid < H12 * EMB) {          // va1/vd1
        int h = gid >> 6, k = gid & 63;
        float s1 = 0.f, s2 = 0.f;
        for (int d = 0; d < EMB; d++) {
            float w = w1[k * D1 + h * EMB + d];
            s1 += w * as1[h * EMB + d];
            s2 += w * ad1[h * EMB + d];
        }
        va1[gid] = s1; vd1[gid] = s2;
        return;
    }
    gid -= H12 * EMB;
    if (gid < H12 * D1) {           // va2/vd2
        int h = gid >> 8, k = gid & 255;
        float s1 = 0.f, s2 = 0.f;
        for (int d = 0; d < EMB; d++) {
            float w = w2[k * D1 + h * EMB + d];
            s1 += w * as2[h * EMB + d];
            s2 += w * ad2[h * EMB + d];
        }
        va2[gid] = s1; vd2[gid] = s2;
        return;
    }
    gid -= H12 * D1;
    if (gid < H3 * D1) {            // va3/vd3
        int h = gid >> 8, k = gid & 255;
        float s1 = 0.f, s2 = 0.f;
        for (int o = 0; o < OUT3; o++) {
            float w = w3[k * D3 + h * OUT3 + o];
            s1 += w * as3[h * OUT3 + o];
            s2 += w * ad3[h * OUT3 + o];
        }
        va3[gid] = s1; vd3[gid] = s2;
    }
}

// ---------------- CSR scan chain ---------------------------------------------
__global__ __launch_bounds__(1024) void deg_part(const int* __restrict__ deg,
                                                 int* __restrict__ bsum) {
    __shared__ int ws[32];
    int t = threadIdx.x, lane = t & 31, w = t >> 5;
    int idx = blockIdx.x * 1024 + t;
    int v = (idx < NNODE) ? deg[idx] : 0;
#pragma unroll
    for (int o = 16; o; o >>= 1) v += __shfl_xor_sync(0xffffffffu, v, o);
    if (lane == 0) ws[w] = v;
    __syncthreads();
    if (t < 32) {
        int s = ws[t];
#pragma unroll
        for (int o = 16; o; o >>= 1) s += __shfl_xor_sync(0xffffffffu, s, o);
        if (t == 0) bsum[blockIdx.x] = s;
    }
}
__global__ void scan_bsum(const int* __restrict__ bsum, int* __restrict__ bpre,
                          int* __restrict__ off, int nblk) {
    int t = threadIdx.x;
    int v = (t < nblk) ? bsum[t] : 0;
    int own = v;
#pragma unroll
    for (int o = 1; o < 32; o <<= 1) {
        int y = __shfl_up_sync(0xffffffffu, v, o);
        if (t >= o) v += y;
    }
    if (t < nblk) bpre[t] = v - own;
    if (t == 31) off[NNODE] = v;
}
__global__ __launch_bounds__(1024) void deg_scan(const int* __restrict__ deg,
                                                 const int* __restrict__ bpre,
                                                 int* __restrict__ off) {
    __shared__ int ws[32];
    int t = threadIdx.x, lane = t & 31, w = t >> 5;
    int idx = blockIdx.x * 1024 + t;
    int v = (idx < NNODE) ? deg[idx] : 0;
    int x = v;
#pragma unroll
    for (int o = 1; o < 32; o <<= 1) {
        int y = __shfl_up_sync(0xffffffffu, x, o);
        if (lane >= o) x += y;
    }
    if (lane == 31) ws[w] = x;
    __syncthreads();
    if (w == 0) {
        int y = ws[lane];
#pragma unroll
        for (int o = 1; o < 32; o <<= 1) {
            int z = __shfl_up_sync(0xffffffffu, y, o);
            if (lane >= o) y += z;
        }
        ws[lane] = y;
    }
    __syncthreads();
    int excl = x - v + (w ? ws[w - 1] : 0) + bpre[blockIdx.x];
    if (idx < NNODE) off[idx] = excl;
}
__global__ void scatter_edges(const int* __restrict__ ei, const int* __restrict__ off,
                              int* __restrict__ cur, int* __restrict__ csrc) {
    int e = blockIdx.x * blockDim.x + threadIdx.x;
    if (e >= ETOT) return;
    int s, d;
    if (e < NEDGE) { s = ei[e]; d = ei[NEDGE + e]; }
    else           { s = d = e - NEDGE; }
    int slot = off[d] + atomicAdd(&cur[d], 1);
    csrc[slot] = s;
}

// ---------------- fp16 tensor GEMM: C = A @ Bt^T -----------------------------
template <int BN>
__global__ __launch_bounds__(256) void gemm_h16(
        const __half* __restrict__ A, const __half* __restrict__ Bt,
        float* __restrict__ C, __half* __restrict__ Ch, const float* __restrict__ bias,
        int M, int K, int lda, int ldb, int ldc,
        int aHS, int bHS, int cHS, int biasHS, int elu) {
    constexpr int AST = 40;
    constexpr int WN = BN / 2;
    constexpr int JT = WN / 8;
    __shared__ __half As[128 * AST];
    __shared__ __half Bs[BN * AST];
    int t = threadIdx.x;
    int warp = t >> 5, lane = t & 31;
    int tg = lane >> 2, t4 = lane & 3;
    int bm = blockIdx.y * 128, bn = blockIdx.x * BN;
    int z = blockIdx.z;
    const __half* Az = A + (size_t)aHS * z;
    const __half* Bz = Bt + (size_t)bHS * z;
    int wm = (warp & 3) * 32, wn = (warp >> 2) * WN;
    float c[2][JT][4];
#pragma unroll
    for (int i = 0; i < 2; i++)
#pragma unroll
        for (int j = 0; j < JT; j++)
#pragma unroll
            for (int q = 0; q < 4; q++) c[i][j][q] = 0.f;

    for (int k0 = 0; k0 < K; k0 += 32) {
#pragma unroll
        for (int i = 0; i < 2; i++) {
            int v = t + 256 * i;
            int row = v >> 2, kc = (v & 3) * 8;
            uint4 u = make_uint4(0u, 0u, 0u, 0u);
            int gr = bm + row;
            if (gr < M) u = *(const uint4*)(Az + (size_t)gr * lda + k0 + kc);
            *(uint4*)&As[row * AST + kc] = u;
        }
#pragma unroll
        for (int i = 0; i < BN / 64; i++) {
            int v = t + 256 * i;
            int row = v >> 2, kc = (v & 3) * 8;
            *(uint4*)&Bs[row * AST + kc] =
                *(const uint4*)(Bz + (size_t)(bn + row) * ldb + k0 + kc);
        }
        __syncthreads();
#pragma unroll
        for (int ks = 0; ks < 2; ks++) {
            int kb = ks * 16;
            unsigned a[2][4], b[JT][2];
#pragma unroll
            for (int i = 0; i < 2; i++) {
                int r = wm + 16 * i + tg;
                a[i][0] = *(const unsigned*)&As[r * AST + kb + 2 * t4];
                a[i][1] = *(const unsigned*)&As[(r + 8) * AST + kb + 2 * t4];
                a[i][2] = *(const unsigned*)&As[r * AST + kb + 2 * t4 + 8];
                a[i][3] = *(const unsigned*)&As[(r + 8) * AST + kb + 2 * t4 + 8];
            }
#pragma unroll
            for (int j = 0; j < JT; j++) {
                int n = wn + 8 * j + tg;
                b[j][0] = *(const unsigned*)&Bs[n * AST + kb + 2 * t4];
                b[j][1] = *(const unsigned*)&Bs[n * AST + kb + 2 * t4 + 8];
            }
#pragma unroll
            for (int i = 0; i < 2; i++)
#pragma unroll
                for (int j = 0; j < JT; j++) {
                    asm volatile(
                        "mma.sync.aligned.m16n8k16.row.col.f32.f16.f16.f32 "
                        "{%0,%1,%2,%3}, {%4,%5,%6,%7}, {%8,%9}, {%0,%1,%2,%3};"
                        : "+f"(c[i][j][0]), "+f"(c[i][j][1]),
                          "+f"(c[i][j][2]), "+f"(c[i][j][3])
                        : "r"(a[i][0]), "r"(a[i][1]), "r"(a[i][2]), "r"(a[i][3]),
                          "r"(b[j][0]), "r"(b[j][1]));
                }
        }
        __syncthreads();
    }
#pragma unroll
    for (int i = 0; i < 2; i++)
#pragma unroll
        for (int j = 0; j < JT; j++) {
            int r = bm + wm + 16 * i + tg;
            int cc = bn + wn + 8 * j + 2 * t4;
            float v0 = c[i][j][0], v1 = c[i][j][1];
            float v2 = c[i][j][2], v3 = c[i][j][3];
            if (bias) {
                float b0 = bias[biasHS * z + cc], b1 = bias[biasHS * z + cc + 1];
                v0 += b0; v1 += b1; v2 += b0; v3 += b1;
            }
            if (elu) {
                v0 = v0 > 0.f ? v0 : expm1f(v0);
                v1 = v1 > 0.f ? v1 : expm1f(v1);
                v2 = v2 > 0.f ? v2 : expm1f(v2);
                v3 = v3 > 0.f ? v3 : expm1f(v3);
            }
            if (C) {
                float* Cz = C + (size_t)cHS * z;
                if (r < M)     *(float2*)(Cz + (size_t)r * ldc + cc)       = make_float2(v0, v1);
                if (r + 8 < M) *(float2*)(Cz + (size_t)(r + 8) * ldc + cc) = make_float2(v2, v3);
            }
            if (Ch) {
                __half* Hz = Ch + (size_t)cHS * z;
                if (r < M)     *(__half2*)(Hz + (size_t)r * ldc + cc)       = __floats2half2_rn(v0, v1);
                if (r + 8 < M) *(__half2*)(Hz + (size_t)(r + 8) * ldc + cc) = __floats2half2_rn(v2, v3);
            }
        }
}

// ---------------- layer-3 GEMM with fused mean-pool epilogue -----------------
__global__ __launch_bounds__(256) void gemm_h16_pool(
        const __half* __restrict__ A, const __half* __restrict__ Bt,
        const int* __restrict__ bat, float* __restrict__ pool,
        int M, int K, int lda, int ldb, int aHS, int bHS) {
    constexpr int BN = 128, AST = 40, WN = 64, JT = 8;
    __shared__ __half As[128 * AST];
    __shared__ __half Bs[BN * AST];
    int t = threadIdx.x;
    int warp = t >> 5, lane = t & 31;
    int tg = lane >> 2, t4 = lane & 3;
    int bm = blockIdx.y * 128;
    int z = blockIdx.z;
    const __half* Az = A + (size_t)aHS * z;
    const __half* Bz = Bt + (size_t)bHS * z;
    int wm = (warp & 3) * 32, wn = (warp >> 2) * WN;
    float c[2][JT][4];
#pragma unroll
    for (int i = 0; i < 2; i++)
#pragma unroll
        for (int j = 0; j < JT; j++)
#pragma unroll
            for (int q = 0; q < 4; q++) c[i][j][q] = 0.f;

    for (int k0 = 0; k0 < K; k0 += 32) {
#pragma unroll
        for (int i = 0; i < 2; i++) {
            int v = t + 256 * i;
            int row = v >> 2, kc = (v & 3) * 8;
            uint4 u = make_uint4(0u, 0u, 0u, 0u);
            int gr = bm + row;
            if (gr < M) u = *(const uint4*)(Az + (size_t)gr * lda + k0 + kc);
            *(uint4*)&As[row * AST + kc] = u;
        }
#pragma unroll
        for (int i = 0; i < 2; i++) {
            int v = t + 256 * i;
            int row = v >> 2, kc = (v & 3) * 8;
            *(uint4*)&Bs[row * AST + kc] =
                *(const uint4*)(Bz + (size_t)row * ldb + k0 + kc);
        }
        __syncthreads();
#pragma unroll
        for (int ks = 0; ks < 2; ks++) {
            int kb = ks * 16;
            unsigned a[2][4], b[JT][2];
#pragma unroll
            for (int i = 0; i < 2; i++) {
                int r = wm + 16 * i + tg;
                a[i][0] = *(const unsigned*)&As[r * AST + kb + 2 * t4];
                a[i][1] = *(const unsigned*)&As[(r + 8) * AST + kb + 2 * t4];
                a[i][2] = *(const unsigned*)&As[r * AST + kb + 2 * t4 + 8];
                a[i][3] = *(const unsigned*)&As[(r + 8) * AST + kb + 2 * t4 + 8];
            }
#pragma unroll
            for (int j = 0; j < JT; j++) {
                int n = wn + 8 * j + tg;
                b[j][0] = *(const unsigned*)&Bs[n * AST + kb + 2 * t4];
                b[j][1] = *(const unsigned*)&Bs[n * AST + kb + 2 * t4 + 8];
            }
#pragma unroll
            for (int i = 0; i < 2; i++)
#pragma unroll
                for (int j = 0; j < JT; j++) {
                    asm volatile(
                        "mma.sync.aligned.m16n8k16.row.col.f32.f16.f16.f32 "
                        "{%0,%1,%2,%3}, {%4,%5,%6,%7}, {%8,%9}, {%0,%1,%2,%3};"
                        : "+f"(c[i][j][0]), "+f"(c[i][j][1]),
                          "+f"(c[i][j][2]), "+f"(c[i][j][3])
                        : "r"(a[i][0]), "r"(a[i][1]), "r"(a[i][2]), "r"(a[i][3]),
                          "r"(b[j][0]), "r"(b[j][1]));
                }
        }
        __syncthreads();
    }
#pragma unroll
    for (int i = 0; i < 2; i++)
#pragma unroll
        for (int j = 0; j < JT; j++) {
            int r = bm + wm + 16 * i + tg;
            int cc = z * 128 + wn + 8 * j + 2 * t4;
            if (r < M) {
                int b = __ldg(&bat[r]);
                red_v2(&pool[(size_t)b * D3P + cc], c[i][j][0], c[i][j][1]);
            }
            if (r + 8 < M) {
                int b = __ldg(&bat[r + 8]);
                red_v2(&pool[(size_t)b * D3P + cc], c[i][j][2], c[i][j][3]);
            }
        }
}

// ---------------- attention logits: thread per node, fp16 rows ---------------
// es/ed[n,h] = dot(featrow, va/vd[h]); va/vd in shared, broadcast access
template <int K, int H>
__global__ __launch_bounds__(256) void attn_h(const __half* __restrict__ feat,
                                              const float* __restrict__ va,
                                              const float* __restrict__ vd,
                                              float* __restrict__ es,
                                              float* __restrict__ ed) {
    constexpr int K8 = K / 8;
    __shared__ float sva[H * K], svd[H * K];
    int t = threadIdx.x;
    for (int i = t; i < H * K; i += 256) { sva[i] = va[i]; svd[i] = vd[i]; }
    __syncthreads();
    int n = blockIdx.x * 256 + t;
    if (n >= NNODE) return;
    const __half* row = feat + (size_t)n * K;
    float e1[H], e2[H];
#pragma unroll
    for (int h = 0; h < H; h++) { e1[h] = 0.f; e2[h] = 0.f; }
    for (int k8 = 0; k8 < K8; k8++) {
        uint4 u = *(const uint4*)(row + k8 * 8);
        __half2 h0 = *(__half2*)&u.x, h1 = *(__half2*)&u.y;
        __half2 h2 = *(__half2*)&u.z, h3 = *(__half2*)&u.w;
        float xv[8];
        xv[0] = __low2float(h0); xv[1] = __high2float(h0);
        xv[2] = __low2float(h1); xv[3] = __high2float(h1);
        xv[4] = __low2float(h2); xv[5] = __high2float(h2);
        xv[6] = __low2float(h3); xv[7] = __high2float(h3);
#pragma unroll
        for (int h = 0; h < H; h++)
#pragma unroll
            for (int p = 0; p < 8; p++) {
                e1[h] += xv[p] * sva[h * K + k8 * 8 + p];
                e2[h] += xv[p] * svd[h * K + k8 * 8 + p];
            }
    }
#pragma unroll
    for (int h = 0; h < H; h++) {
        es[n * H + h] = e1[h];
        ed[n * H + h] = e2[h];
    }
}

// ---------------- single-pass per-head x aggregation (layers 1 & 3) ---------
template <int H, int HPL>
__global__ __launch_bounds__(256) void gat_agg_xh(const int* __restrict__ off,
                                                  const int* __restrict__ csrc,
                                                  const float* __restrict__ es,
                                                  const float* __restrict__ ed,
                                                  const __half* __restrict__ xin,
                                                  __half* __restrict__ agg) {
    constexpr int KH = 32 * HPL;
    int gw = (blockIdx.x * blockDim.x + threadIdx.x) >> 5;
    int lane = threadIdx.x & 31;
    if (gw >= NNODE) return;
    int o0 = off[gw], o1 = off[gw + 1];
    float edv = (lane < H) ? __ldg(&ed[gw * H + lane]) : 0.f;
    float smv = 0.f;
    float acc[H][HPL];
#pragma unroll
    for (int h = 0; h < H; h++)
#pragma unroll
        for (int p = 0; p < HPL; p++) acc[h][p] = 0.f;

    for (int i = o0; i < o1; i++) {
        int s = __ldg(&csrc[i]);
        float a = 0.f;
        if (lane < H) {
            float v = __ldg(&es[s * H + lane]) + edv;
            v = v > 0.f ? v : 0.2f * v;
            a = __expf(v);
            smv += a;
        }
        float ah[H];
#pragma unroll
        for (int h = 0; h < H; h++) ah[h] = __shfl_sync(0xffffffffu, a, h);
        const __half* row = xin + (size_t)s * KH + lane * HPL;
        float xv[HPL];
        if (HPL == 2) {
            __half2 hv = *(const __half2*)row;
            xv[0] = __low2float(hv); xv[1] = __high2float(hv);
        } else {
            uint4 u = *(const uint4*)row;
            __half2 h0 = *(__half2*)&u.x, h1 = *(__half2*)&u.y;
            __half2 h2 = *(__half2*)&u.z, h3 = *(__half2*)&u.w;
            xv[0] = __low2float(h0); xv[1] = __high2float(h0);
            xv[2] = __low2float(h1); xv[3] = __high2float(h1);
            xv[4] = __low2float(h2); xv[5] = __high2float(h2);
            xv[6] = __low2float(h3); xv[7] = __high2float(h3);
        }
#pragma unroll
        for (int h = 0; h < H; h++)
#pragma unroll
            for (int p = 0; p < HPL; p++) acc[h][p] += ah[h] * xv[p];
    }
    float inv[H];
#pragma unroll
    for (int h = 0; h < H; h++)
        inv[h] = 1.f / __shfl_sync(0xffffffffu, smv, h);
    __half* orow = agg + (size_t)gw * (H * KH);
#pragma unroll
    for (int h = 0; h < H; h++)
#pragma unroll
        for (int p = 0; p < HPL; p += 2)
            *(__half2*)(orow + h * KH + lane * HPL + p) =
                __floats2half2_rn(acc[h][p] * inv[h], acc[h][p + 1] * inv[h]);
}

// ---------------- single-pass layer-2 aggregation (fp16 out only) ------------
__global__ __launch_bounds__(256) void gat_agg_ph(const int* __restrict__ off,
                                                  const int* __restrict__ csrc,
                                                  const float* __restrict__ es,
                                                  const float* __restrict__ ed,
                                                  const __half* __restrict__ proj,
                                                  const float* __restrict__ bias,
                                                  __half* __restrict__ outh) {
    constexpr int H = H12;
    int gw = (blockIdx.x * blockDim.x + threadIdx.x) >> 5;
    int lane = threadIdx.x & 31;
    if (gw >= NNODE) return;
    int o0 = off[gw], o1 = off[gw + 1];
    float edv = (lane < H) ? __ldg(&ed[gw * H + lane]) : 0.f;
    float smv = 0.f;
    float acc[8];
#pragma unroll
    for (int p = 0; p < 8; p++) acc[p] = 0.f;
    int myhead = lane >> 3;

    for (int i = o0; i < o1; i++) {
        int s = __ldg(&csrc[i]);
        float a = 0.f;
        if (lane < H) {
            float v = __ldg(&es[s * H + lane]) + edv;
            v = v > 0.f ? v : 0.2f * v;
            a = __expf(v);
            smv += a;
        }
        float av = __shfl_sync(0xffffffffu, a, myhead);
        uint4 u = *(const uint4*)(proj + (size_t)s * D1 + lane * 8);
        __half2 h0 = *(__half2*)&u.x, h1 = *(__half2*)&u.y;
        __half2 h2 = *(__half2*)&u.z, h3 = *(__half2*)&u.w;
        acc[0] += av * __low2float(h0); acc[1] += av * __high2float(h0);
        acc[2] += av * __low2float(h1); acc[3] += av * __high2float(h1);
        acc[4] += av * __low2float(h2); acc[5] += av * __high2float(h2);
        acc[6] += av * __low2float(h3); acc[7] += av * __high2float(h3);
    }
    float inv = 1.f / __shfl_sync(0xffffffffu, smv, myhead);
    __half* hrow = outh + (size_t)gw * D1 + lane * 8;
#pragma unroll
    for (int p = 0; p < 8; p += 2) {
        float v0 = acc[p] * inv + bias[lane * 8 + p];
        float v1 = acc[p + 1] * inv + bias[lane * 8 + p + 1];
        v0 = v0 > 0.f ? v0 : expm1f(v0);
        v1 = v1 > 0.f ? v1 : expm1f(v1);
        *(__half2*)(hrow + p) = __floats2half2_rn(v0, v1);
    }
}

// ---------------- classifier head --------------------------------------------
__global__ void head_kernel(const float* __restrict__ pool, const float* __restrict__ cnt,
                            const float* __restrict__ b3p,
                            const float* __restrict__ wp, const float* __restrict__ bp,
                            float* __restrict__ out) {
    __shared__ float gm[OUT3];
    int b = blockIdx.x;
    float inv = 1.f / fmaxf(cnt[b], 1.f);
    for (int o = threadIdx.x; o < OUT3; o += blockDim.x) {
        float s = 0.f, sb = 0.f;
#pragma unroll
        for (int h = 0; h < H3; h++) {
            s += pool[b * D3P + h * 128 + o];
            sb += b3p[h * 128 + o];
        }
        gm[o] = (s * inv + sb) * (1.f / H3);
    }
    __syncthreads();
    if (threadIdx.x < NCLS) {
        float acc = bp[threadIdx.x];
        for (int o = 0; o < OUT3; o++) acc += gm[o] * wp[o * NCLS + threadIdx.x];
        out[b * NCLS + threadIdx.x] = acc;
    }
}

// ---------------- host orchestration ----------------------------------------
extern "C" void kernel_launch(void* const* d_in, const int* in_sizes, int n_in,
                              void* d_out, int out_size) {
    const int*   x    = (const int*)d_in[0];
    const int*   nd   = (const int*)d_in[1];
    const int*   ei   = (const int*)d_in[2];
    const int*   bat  = (const int*)d_in[3];
    const float* nemb = (const float*)d_in[4];
    const float* demb = (const float*)d_in[5];
    const float* w1   = (const float*)d_in[6];
    const float* as1  = (const float*)d_in[7];
    const float* ad1  = (const float*)d_in[8];
    const float* b1   = (const float*)d_in[9];
    const float* w2   = (const float*)d_in[10];
    const float* as2  = (const float*)d_in[11];
    const float* ad2  = (const float*)d_in[12];
    const float* b2   = (const float*)d_in[13];
    const float* w3   = (const float*)d_in[14];
    const float* as3  = (const float*)d_in[15];
    const float* ad3  = (const float*)d_in[16];
    const float* b3   = (const float*)d_in[17];
    const float* wp   = (const float*)d_in[18];
    const float* bp   = (const float*)d_in[19];
    float* out = (float*)d_out;

    float *es, *ed, *va1, *vd1, *va2, *vd2, *va3, *vd3, *b3p, *pool, *cnt;
    __half *x0h, *p1h, *feath, *projh, *feat2h, *agg3h, *w1t, *w2t, *w3t;
    int *deg, *off, *cur, *csrc, *bsum, *bpre;
    cudaGetSymbolAddress((void**)&x0h,   g_x0h);
    cudaGetSymbolAddress((void**)&p1h,   g_p1h);
    cudaGetSymbolAddress((void**)&feath, g_feath);
    cudaGetSymbolAddress((void**)&projh, g_projh);
    cudaGetSymbolAddress((void**)&feat2h,g_feat2h);
    cudaGetSymbolAddress((void**)&agg3h, g_agg3h);
    cudaGetSymbolAddress((void**)&es,    g_es);
    cudaGetSymbolAddress((void**)&ed,    g_ed);
    cudaGetSymbolAddress((void**)&va1,   g_va1);
    cudaGetSymbolAddress((void**)&vd1,   g_vd1);
    cudaGetSymbolAddress((void**)&va2,   g_va2);
    cudaGetSymbolAddress((void**)&vd2,   g_vd2);
    cudaGetSymbolAddress((void**)&va3,   g_va3);
    cudaGetSymbolAddress((void**)&vd3,   g_vd3);
    cudaGetSymbolAddress((void**)&w1t,   g_w1t);
    cudaGetSymbolAddress((void**)&w2t,   g_w2t);
    cudaGetSymbolAddress((void**)&w3t,   g_w3t);
    cudaGetSymbolAddress((void**)&b3p,   g_b3p);
    cudaGetSymbolAddress((void**)&pool,  g_pool);
    cudaGetSymbolAddress((void**)&cnt,   g_cnt);
    cudaGetSymbolAddress((void**)&deg,   g_deg);
    cudaGetSymbolAddress((void**)&off,   g_off);
    cudaGetSymbolAddress((void**)&cur,   g_cur);
    cudaGetSymbolAddress((void**)&csrc,  g_csrc);
    cudaGetSymbolAddress((void**)&bsum,  g_bsum);
    cudaGetSymbolAddress((void**)&bpre,  g_bpre);

    const int TB = 256;
    const int eb = (ETOT + TB - 1) / TB;
    const int nb = (NNODE * 32 + TB - 1) / TB;   // warp per node
    const int hb = (NNODE + TB - 1) / TB;        // thread per node
    const int SB = (NNODE + 1023) / 1024;
    const int MB = (NNODE + 127) / 128;

    cudaMemsetAsync(deg, 0, NNODE * 4);
    cudaMemsetAsync(cur, 0, NNODE * 4);
    cudaMemsetAsync(pool, 0, NB * D3P * 4);
    cudaMemsetAsync(cnt, 0, NB * 4);

    setup_all<<<(SETUP_TOTAL + TB - 1) / TB, TB>>>(
        x, nd, nemb, demb, ei, bat,
        w1, as1, ad1, w2, as2, ad2, w3, as3, ad3, b3,
        x0h, deg, cnt, w1t, w2t, w3t, b3p,
        va1, vd1, va2, vd2, va3, vd3);
    deg_part<<<SB, 1024>>>(deg, bsum);
    scan_bsum<<<1, 32>>>(bsum, bpre, off, SB);
    deg_scan<<<SB, 1024>>>(deg, bpre, off);
    scatter_edges<<<eb, TB>>>(ei, off, cur, csrc);

    // ---- layer 1 ----
    attn_h<EMB, H12><<<hb, TB>>>(x0h, va1, vd1, es, ed);
    gat_agg_xh<H12, 2><<<nb, TB>>>(off, csrc, es, ed, x0h, p1h);
    {
        dim3 g(1, MB, H12);
        gemm_h16<64><<<g, 256>>>(p1h, w1t, nullptr, feath, b1, NNODE, EMB,
                                 D1, EMB, D1, EMB, 64 * EMB, EMB, EMB, 1);
    }

    // ---- layer 2 ----
    {
        dim3 g(2, MB, 1);
        gemm_h16<128><<<g, 256>>>(feath, w2t, nullptr, projh, nullptr, NNODE, D1,
                                  D1, D1, D1, 0, 0, 0, 0, 0);
    }
    attn_h<D1, H12><<<hb, TB>>>(feath, va2, vd2, es, ed);
    gat_agg_ph<<<nb, TB>>>(off, csrc, es, ed, projh, b2, feat2h);

    // ---- layer 3 (GEMM + fused mean-pool) ----
    attn_h<D1, H3><<<hb, TB>>>(feat2h, va3, vd3, es, ed);
    gat_agg_xh<H3, 8><<<nb, TB>>>(off, csrc, es, ed, feat2h, agg3h);
    {
        dim3 g(1, MB, H3);
        gemm_h16_pool<<<g, 256>>>(agg3h, w3t, bat, pool, NNODE, D1,
                                  H3 * D1, D1, D1, 128 * D1);
    }

    // ---- classifier head ----
    head_kernel<<<NB, 128>>>(pool, cnt, b3p, wp, bp, out);
}